// round 2
// baseline (speedup 1.0000x reference)
#include <cuda_runtime.h>

// Problem constants (fixed shapes from reference)
#define BB  4
#define CC  256
#define NN  4096
#define CTT 256
#define KO  512   // 2*CT for output projection

// Scratch (allocation-free: __device__ globals — sanctioned by harness rules)
__device__ float g_q[(size_t)BB * NN * CTT];            // (B,N,CT)
__device__ float g_k[(size_t)BB * NN * CTT];            // (B,N,CT)  (k[b][m][c])
__device__ float g_v[(size_t)BB * NN * CTT];            // (B,N,CT)
__device__ float g_ctx[(size_t)BB * NN * CTT];          // (B,N,CT)  ctx2[b][n][c]
__device__ float g_sim[(size_t)BB * NN * NN];           // (B,N,N)   256 MB

// ---------------------------------------------------------------------------
// Common tiling: CTA computes 128 (rows) x 64 (cols), K-step 16.
// 256 threads as 16x16; each thread owns an 8(row) x 4(col) register tile.
// As[16][132]: 128-wide operand (rows).  Bs[16][68]: 64-wide operand (cols).
// Row strides 132/68 floats keep float4 alignment (528/272 bytes % 16 == 0)
// and limit STS bank conflicts to 2-way on the kk-fast load patterns.
// ---------------------------------------------------------------------------

#define INNER_MMA()                                                         \
    _Pragma("unroll")                                                       \
    for (int kk = 0; kk < 16; kk++) {                                       \
        const float4* Ar = reinterpret_cast<const float4*>(&As[kk][0]);     \
        const float4* Br = reinterpret_cast<const float4*>(&Bs[kk][0]);     \
        float4 a0 = Ar[ty * 2];                                             \
        float4 a1 = Ar[ty * 2 + 1];                                         \
        float4 bv = Br[tx];                                                 \
        float ar[8] = {a0.x, a0.y, a0.z, a0.w, a1.x, a1.y, a1.z, a1.w};     \
        float bc[4] = {bv.x, bv.y, bv.z, bv.w};                             \
        _Pragma("unroll")                                                   \
        for (int r = 0; r < 8; r++)                                         \
            _Pragma("unroll")                                               \
            for (int j = 0; j < 4; j++)                                     \
                acc[r][j] += ar[r] * bc[j];                                 \
    }

// ---------------------------------------------------------------------------
// K1: QKV projection.  dst[b][n][o] = sum_c W[o][c] * x[b][c][n]
// grid: (NN/128, CTT/64, BB*3); z selects (b, which weight)
// ---------------------------------------------------------------------------
__global__ __launch_bounds__(256) void qkv_kernel(
    const float* __restrict__ x, const float* __restrict__ Wq,
    const float* __restrict__ Wk, const float* __restrict__ Wv)
{
    const int w = blockIdx.z % 3;
    const int b = blockIdx.z / 3;
    const float* __restrict__ W = (w == 0) ? Wq : (w == 1) ? Wk : Wv;
    float* dst = (w == 0) ? g_q : (w == 1) ? g_k : g_v;

    const int n0 = blockIdx.x * 128;
    const int o0 = blockIdx.y * 64;
    const int tid = threadIdx.x;
    const int tx = tid & 15, ty = tid >> 4;

    __shared__ float As[16][132];
    __shared__ float Bs[16][68];

    float acc[8][4];
#pragma unroll
    for (int r = 0; r < 8; r++)
#pragma unroll
        for (int j = 0; j < 4; j++) acc[r][j] = 0.f;

    const float* __restrict__ xb = x + (size_t)b * CC * NN;

    for (int ck = 0; ck < CC; ck += 16) {
        // As[kk][nn] = x[b][ck+kk][n0+nn]  (nn fast -> coalesced, conflict-free STS)
#pragma unroll
        for (int i = 0; i < 8; i++) {
            int idx = tid + i * 256;
            int nn = idx & 127, kk = idx >> 7;
            As[kk][nn] = xb[(ck + kk) * NN + n0 + nn];
        }
        // Bs[kk][oo] = W[(o0+oo)*C + ck+kk]  (kk fast -> 64B chunks)
#pragma unroll
        for (int i = 0; i < 4; i++) {
            int idx = tid + i * 256;
            int kk = idx & 15, oo = idx >> 4;
            Bs[kk][oo] = W[(o0 + oo) * CC + ck + kk];
        }
        __syncthreads();
        INNER_MMA();
        __syncthreads();
    }

#pragma unroll
    for (int r = 0; r < 8; r++) {
        float4 o4 = make_float4(acc[r][0], acc[r][1], acc[r][2], acc[r][3]);
        *reinterpret_cast<float4*>(
            &dst[((size_t)b * NN + n0 + ty * 8 + r) * CTT + o0 + tx * 4]) = o4;
    }
}

// ---------------------------------------------------------------------------
// K2: sim[b][n][m] = scale * sum_c q[b][n][c] * k[b][m][c]
// grid: (NN/128, NN/64, BB)
// ---------------------------------------------------------------------------
__global__ __launch_bounds__(256) void sim_kernel()
{
    const int b = blockIdx.z;
    const int n0 = blockIdx.x * 128;
    const int m0 = blockIdx.y * 64;
    const int tid = threadIdx.x;
    const int tx = tid & 15, ty = tid >> 4;

    const float* __restrict__ q = g_q + (size_t)b * NN * CTT;
    const float* __restrict__ k = g_k + (size_t)b * NN * CTT;

    __shared__ float As[16][132];
    __shared__ float Bs[16][68];

    float acc[8][4];
#pragma unroll
    for (int r = 0; r < 8; r++)
#pragma unroll
        for (int j = 0; j < 4; j++) acc[r][j] = 0.f;

    for (int ck = 0; ck < CTT; ck += 16) {
#pragma unroll
        for (int i = 0; i < 8; i++) {
            int idx = tid + i * 256;
            int kk = idx & 15, nn = idx >> 4;
            As[kk][nn] = q[(n0 + nn) * CTT + ck + kk];
        }
#pragma unroll
        for (int i = 0; i < 4; i++) {
            int idx = tid + i * 256;
            int kk = idx & 15, mm = idx >> 4;
            Bs[kk][mm] = k[(m0 + mm) * CTT + ck + kk];
        }
        __syncthreads();
        INNER_MMA();
        __syncthreads();
    }

    float* __restrict__ simb = g_sim + (size_t)b * NN * NN;
    const float scale = 0.0625f;  // CT^-0.5 = 1/16
#pragma unroll
    for (int r = 0; r < 8; r++) {
        float4 o4 = make_float4(acc[r][0] * scale, acc[r][1] * scale,
                                acc[r][2] * scale, acc[r][3] * scale);
        *reinterpret_cast<float4*>(
            &simb[(size_t)(n0 + ty * 8 + r) * NN + m0 + tx * 4]) = o4;
    }
}

// ---------------------------------------------------------------------------
// K3: rowwise softmax over 4096 elements. grid: BB*NN blocks, 256 threads.
// ---------------------------------------------------------------------------
__global__ __launch_bounds__(256) void softmax_kernel()
{
    float* __restrict__ p = g_sim + (size_t)blockIdx.x * NN;
    float4* p4 = reinterpret_cast<float4*>(p);
    const int tid = threadIdx.x;
    __shared__ float sh[8];

    float4 v[4];
#pragma unroll
    for (int j = 0; j < 4; j++) v[j] = p4[tid + 256 * j];

    float mx = -3.4e38f;
#pragma unroll
    for (int j = 0; j < 4; j++) {
        mx = fmaxf(mx, fmaxf(fmaxf(v[j].x, v[j].y), fmaxf(v[j].z, v[j].w)));
    }
#pragma unroll
    for (int off = 16; off; off >>= 1)
        mx = fmaxf(mx, __shfl_xor_sync(0xffffffffu, mx, off));
    if ((tid & 31) == 0) sh[tid >> 5] = mx;
    __syncthreads();
    if (tid < 32) {
        float t = (tid < 8) ? sh[tid] : -3.4e38f;
#pragma unroll
        for (int off = 4; off; off >>= 1)
            t = fmaxf(t, __shfl_xor_sync(0xffffffffu, t, off));
        if (tid == 0) sh[0] = t;
    }
    __syncthreads();
    mx = sh[0];
    __syncthreads();

    float s = 0.f;
#pragma unroll
    for (int j = 0; j < 4; j++) {
        v[j].x = __expf(v[j].x - mx);
        v[j].y = __expf(v[j].y - mx);
        v[j].z = __expf(v[j].z - mx);
        v[j].w = __expf(v[j].w - mx);
        s += v[j].x + v[j].y + v[j].z + v[j].w;
    }
#pragma unroll
    for (int off = 16; off; off >>= 1)
        s += __shfl_xor_sync(0xffffffffu, s, off);
    if ((tid & 31) == 0) sh[tid >> 5] = s;
    __syncthreads();
    if (tid < 32) {
        float t = (tid < 8) ? sh[tid] : 0.f;
#pragma unroll
        for (int off = 4; off; off >>= 1)
            t += __shfl_xor_sync(0xffffffffu, t, off);
        if (tid == 0) sh[0] = t;
    }
    __syncthreads();
    const float inv = 1.0f / sh[0];

#pragma unroll
    for (int j = 0; j < 4; j++) {
        v[j].x *= inv; v[j].y *= inv; v[j].z *= inv; v[j].w *= inv;
        p4[tid + 256 * j] = v[j];
    }
}

// ---------------------------------------------------------------------------
// K4: ctx2[b][n][c] = sum_m P[b][n][m] * v[b][m][c]
// grid: (NN/128, CTT/64, BB)
// ---------------------------------------------------------------------------
__global__ __launch_bounds__(256) void ctx_kernel()
{
    const int b = blockIdx.z;
    const int n0 = blockIdx.x * 128;
    const int c0 = blockIdx.y * 64;
    const int tid = threadIdx.x;
    const int tx = tid & 15, ty = tid >> 4;

    const float* __restrict__ P = g_sim + (size_t)b * NN * NN;
    const float* __restrict__ v = g_v + (size_t)b * NN * CTT;

    __shared__ float As[16][132];
    __shared__ float Bs[16][68];

    float acc[8][4];
#pragma unroll
    for (int r = 0; r < 8; r++)
#pragma unroll
        for (int j = 0; j < 4; j++) acc[r][j] = 0.f;

    for (int mk = 0; mk < NN; mk += 16) {
#pragma unroll
        for (int i = 0; i < 8; i++) {
            int idx = tid + i * 256;
            int kk = idx & 15, nn = idx >> 4;
            As[kk][nn] = P[(size_t)(n0 + nn) * NN + mk + kk];
        }
#pragma unroll
        for (int i = 0; i < 4; i++) {
            int idx = tid + i * 256;
            int cc = idx & 63, kk = idx >> 6;
            Bs[kk][cc] = v[(mk + kk) * CTT + c0 + cc];
        }
        __syncthreads();
        INNER_MMA();
        __syncthreads();
    }

#pragma unroll
    for (int r = 0; r < 8; r++) {
        float4 o4 = make_float4(acc[r][0], acc[r][1], acc[r][2], acc[r][3]);
        *reinterpret_cast<float4*>(
            &g_ctx[((size_t)b * NN + n0 + ty * 8 + r) * CTT + c0 + tx * 4]) = o4;
    }
}

// ---------------------------------------------------------------------------
// K5: out[b][o][n] = sum_{c<256} Wo[o][c]*ctx2[b][n][c]
//                  + sum_{c<256} Wo[o][256+c]*x[b][c][n]
// grid: (CC/128, NN/64, BB).  Rows = o (from Wo), cols = n.
// ---------------------------------------------------------------------------
__global__ __launch_bounds__(256) void out_kernel(
    const float* __restrict__ x, const float* __restrict__ Wo,
    float* __restrict__ out)
{
    const int b = blockIdx.z;
    const int o0 = blockIdx.x * 128;
    const int n0 = blockIdx.y * 64;
    const int tid = threadIdx.x;
    const int tx = tid & 15, ty = tid >> 4;

    const float* __restrict__ ctx = g_ctx + (size_t)b * NN * CTT;
    const float* __restrict__ xb = x + (size_t)b * CC * NN;

    __shared__ float As[16][132];  // weight rows (o)
    __shared__ float Bs[16][68];   // data cols (n)

    float acc[8][4];
#pragma unroll
    for (int r = 0; r < 8; r++)
#pragma unroll
        for (int j = 0; j < 4; j++) acc[r][j] = 0.f;

    for (int ck = 0; ck < KO; ck += 16) {
#pragma unroll
        for (int i = 0; i < 8; i++) {
            int idx = tid + i * 256;
            int kk = idx & 15, oo = idx >> 4;
            As[kk][oo] = Wo[(o0 + oo) * KO + ck + kk];
        }
        if (ck < CTT) {
            // ctx2 phase: c-fast in memory
#pragma unroll
            for (int i = 0; i < 4; i++) {
                int idx = tid + i * 256;
                int kk = idx & 15, nn = idx >> 4;
                Bs[kk][nn] = ctx[(n0 + nn) * CTT + ck + kk];
            }
        } else {
            // x phase: n-fast in memory
#pragma unroll
            for (int i = 0; i < 4; i++) {
                int idx = tid + i * 256;
                int nn = idx & 63, kk = idx >> 6;
                Bs[kk][nn] = xb[(ck - CTT + kk) * NN + n0 + nn];
            }
        }
        __syncthreads();
        INNER_MMA();
        __syncthreads();
    }

#pragma unroll
    for (int r = 0; r < 8; r++) {
        float4 o4 = make_float4(acc[r][0], acc[r][1], acc[r][2], acc[r][3]);
        *reinterpret_cast<float4*>(
            &out[((size_t)b * CC + o0 + ty * 8 + r) * NN + n0 + tx * 4]) = o4;
    }
}

// ---------------------------------------------------------------------------
extern "C" void kernel_launch(void* const* d_in, const int* in_sizes, int n_in,
                              void* d_out, int out_size)
{
    const float* x  = (const float*)d_in[0];
    const float* Wq = (const float*)d_in[1];
    const float* Wk = (const float*)d_in[2];
    const float* Wv = (const float*)d_in[3];
    const float* Wo = (const float*)d_in[4];
    float* out = (float*)d_out;

    dim3 blk(256);
    qkv_kernel<<<dim3(NN / 128, CTT / 64, BB * 3), blk>>>(x, Wq, Wk, Wv);
    sim_kernel<<<dim3(NN / 128, NN / 64, BB), blk>>>();
    softmax_kernel<<<dim3(BB * NN), blk>>>();
    ctx_kernel<<<dim3(NN / 128, CTT / 64, BB), blk>>>();
    out_kernel<<<dim3(CC / 128, NN / 64, BB), blk>>>(x, Wo, out);
}

// round 4
// speedup vs baseline: 2.1504x; 2.1504x over previous
#include <cuda_runtime.h>
#include <cuda_bf16.h>
#include <cstdint>

#define BBq 4
#define CCq 256
#define NNq 4096
#define CTq 256

// ---------------- scratch (allocation-free device globals) ----------------
__device__ float g_xt [(size_t)BBq * NNq * CCq];   // (B,N,C)  = x^T
__device__ float g_q  [(size_t)BBq * NNq * CTq];   // (B,N,CT)
__device__ float g_k  [(size_t)BBq * NNq * CTq];   // (B,N,CT)
__device__ float g_vt [(size_t)BBq * CTq * NNq];   // (B,CT,N) = v^T
__device__ float g_ctx[(size_t)BBq * NNq * CTq];   // (B,N,CT)
__device__ float g_sim[(size_t)BBq * NNq * NNq];   // (B,N,N)

// ---------------- helpers ----------------
__device__ __forceinline__ void split2(float v0, float v1,
                                       uint32_t& whi, uint32_t& wlo) {
    uint32_t h0 = (uint32_t)__bfloat16_as_ushort(__float2bfloat16(v0));
    uint32_t h1 = (uint32_t)__bfloat16_as_ushort(__float2bfloat16(v1));
    float h0f = __uint_as_float(h0 << 16);
    float h1f = __uint_as_float(h1 << 16);
    uint32_t l0 = (uint32_t)__bfloat16_as_ushort(__float2bfloat16(v0 - h0f));
    uint32_t l1 = (uint32_t)__bfloat16_as_ushort(__float2bfloat16(v1 - h1f));
    whi = h0 | (h1 << 16);
    wlo = l0 | (l1 << 16);
}

__device__ __forceinline__ void mma_bf16(float* d, const uint32_t* a,
                                         const uint32_t* b) {
    asm volatile(
        "mma.sync.aligned.m16n8k16.row.col.f32.bf16.bf16.f32 "
        "{%0,%1,%2,%3}, {%4,%5,%6,%7}, {%8,%9}, {%0,%1,%2,%3};"
        : "+f"(d[0]), "+f"(d[1]), "+f"(d[2]), "+f"(d[3])
        : "r"(a[0]), "r"(a[1]), "r"(a[2]), "r"(a[3]), "r"(b[0]), "r"(b[1]));
}

// ---------------- unified split-bf16 GEMM ----------------
// D[128 rows, 128 cols] = A[rows, K] * B[cols, K]^T  (both K-major fp32).
// A may be a K-concat of A1 (first KA1) and A2. 3 MMAs per fragment (split).
// MODE 0: D[row*ldd + col] = acc*scale.   MODE 2: D[col*ldd + row] = acc*scale.
//
// SMEM per buffer (32 KB): fragment-order planes
//   Ahi @ 0     : [8 mblk][2 kstep][32 slot][4 words]  (slot = lane^kstep)
//   Alo @ 8192
//   Bhi @ 16384 : [16 nblk][2 kstep][32 slot][2 words]
//   Blo @ 24576
#define BUF_BYTES 32768
#define SMEM_TOTAL (2 * BUF_BYTES)

template <int MODE>
__global__ __launch_bounds__(256, 1) void gemm_bf16x3(
    const float* __restrict__ A1, int lda1, long long sA1,
    const float* __restrict__ A2, int lda2, long long sA2, int KA1,
    const float* __restrict__ Bp, int ldb, long long sB,
    float* __restrict__ Dp, int ldd, long long sD,
    int K, float scale)
{
    extern __shared__ char sm[];
    const int tid = threadIdx.x;
    const int wid = tid >> 5, lane = tid & 31;
    const int row0 = blockIdx.x * 128;
    const int col0 = blockIdx.y * 128;
    const int b = blockIdx.z;

    const float* __restrict__ Ab1 = A1 + (long long)b * sA1;
    const float* __restrict__ Ab2 = A2 ? (A2 + (long long)b * sA2) : A1;
    const float* __restrict__ Bb = Bp + (long long)b * sB + (size_t)col0 * ldb;
    float* __restrict__ Db = Dp + (long long)b * sD;

    // ---- staging index precompute (4 float4 loads each for A and B) ----
    int m_[4], c4_[4];
    uint32_t ao0[4], ao1[4], bo0[4], bo1[4];
#pragma unroll
    for (int i = 0; i < 4; i++) {
        int q = tid + i * 256;
        int m = q >> 3;
        int c4 = (q & 7) * 4;
        int ks = c4 >> 4;
        int k8 = (c4 >> 3) & 1;
        int L = (m & 7) * 4 + ((c4 & 7) >> 1);
        int regA = ((m >> 3) & 1) + 2 * k8;
        m_[i] = m; c4_[i] = c4;
        ao0[i] = (m >> 4) * 1024 + ks * 512 + (uint32_t)((L ^ ks)) * 16 + regA * 4;
        ao1[i] = (m >> 4) * 1024 + ks * 512 + (uint32_t)(((L + 1) ^ ks)) * 16 + regA * 4;
        bo0[i] = (m >> 3) * 512 + ks * 256 + (uint32_t)((L ^ ks)) * 8 + k8 * 4;
        bo1[i] = (m >> 3) * 512 + ks * 256 + (uint32_t)(((L + 1) ^ ks)) * 8 + k8 * 4;
    }

    // warp tiling: 2 m-warps x 4 n-warps; warp tile 64x32
    const int wm = (wid & 1) * 4;   // mblk base (4 x m16)
    const int wn = (wid >> 1) * 4;  // nblk base (4 x n8)

    float acc[4][4][4];
#pragma unroll
    for (int mf = 0; mf < 4; mf++)
#pragma unroll
        for (int nf = 0; nf < 4; nf++)
#pragma unroll
            for (int r = 0; r < 4; r++) acc[mf][nf][r] = 0.f;

    const int nch = K / 32;

    // ---- stage chunk 0 ----
    {
        const float* Ab = (0 < KA1) ? Ab1 : Ab2;
        int lda_ = (0 < KA1) ? lda1 : lda2;
#pragma unroll
        for (int i = 0; i < 4; i++) {
            float4 av = *reinterpret_cast<const float4*>(
                Ab + (size_t)(row0 + m_[i]) * lda_ + c4_[i]);
            float4 bv = *reinterpret_cast<const float4*>(
                Bb + (size_t)m_[i] * ldb + c4_[i]);
            uint32_t h0, l0, h1, l1;
            split2(av.x, av.y, h0, l0); split2(av.z, av.w, h1, l1);
            *(uint32_t*)(sm + ao0[i]) = h0;
            *(uint32_t*)(sm + ao1[i]) = h1;
            *(uint32_t*)(sm + 8192 + ao0[i]) = l0;
            *(uint32_t*)(sm + 8192 + ao1[i]) = l1;
            split2(bv.x, bv.y, h0, l0); split2(bv.z, bv.w, h1, l1);
            *(uint32_t*)(sm + 16384 + bo0[i]) = h0;
            *(uint32_t*)(sm + 16384 + bo1[i]) = h1;
            *(uint32_t*)(sm + 24576 + bo0[i]) = l0;
            *(uint32_t*)(sm + 24576 + bo1[i]) = l1;
        }
    }
    __syncthreads();

    for (int c = 0; c < nch; c++) {
        char* buf = sm + (c & 1) * BUF_BYTES;
        char* nbuf = sm + ((c + 1) & 1) * BUF_BYTES;

        // prefetch chunk c+1 into registers
        float4 av[4], bv[4];
        const bool more = (c + 1 < nch);
        if (more) {
            int kc = (c + 1) * 32;
            const float* Ab; int lda_; int kl;
            if (kc < KA1) { Ab = Ab1; lda_ = lda1; kl = kc; }
            else          { Ab = Ab2; lda_ = lda2; kl = kc - KA1; }
#pragma unroll
            for (int i = 0; i < 4; i++) {
                av[i] = *reinterpret_cast<const float4*>(
                    Ab + (size_t)(row0 + m_[i]) * lda_ + kl + c4_[i]);
                bv[i] = *reinterpret_cast<const float4*>(
                    Bb + (size_t)m_[i] * ldb + kc + c4_[i]);
            }
        }

        // ---- compute current chunk ----
#pragma unroll
        for (int ks = 0; ks < 2; ks++) {
            const uint32_t ls = (uint32_t)(lane ^ ks);
            uint32_t ahi[4][4], alo[4][4], bhi[4][2], blo[4][2];
#pragma unroll
            for (int mf = 0; mf < 4; mf++) {
                const char* pa = buf + (wm + mf) * 1024 + ks * 512 + ls * 16;
                uint4 t = *(const uint4*)pa;
                ahi[mf][0] = t.x; ahi[mf][1] = t.y; ahi[mf][2] = t.z; ahi[mf][3] = t.w;
                uint4 u = *(const uint4*)(pa + 8192);
                alo[mf][0] = u.x; alo[mf][1] = u.y; alo[mf][2] = u.z; alo[mf][3] = u.w;
            }
#pragma unroll
            for (int nf = 0; nf < 4; nf++) {
                const char* pb = buf + 16384 + (wn + nf) * 512 + ks * 256 + ls * 8;
                uint2 t = *(const uint2*)pb;
                bhi[nf][0] = t.x; bhi[nf][1] = t.y;
                uint2 u = *(const uint2*)(pb + 8192);
                blo[nf][0] = u.x; blo[nf][1] = u.y;
            }
#pragma unroll
            for (int mf = 0; mf < 4; mf++)
#pragma unroll
                for (int nf = 0; nf < 4; nf++) {
                    mma_bf16(acc[mf][nf], ahi[mf], bhi[nf]);
                    mma_bf16(acc[mf][nf], ahi[mf], blo[nf]);
                    mma_bf16(acc[mf][nf], alo[mf], bhi[nf]);
                }
        }

        // ---- store prefetched chunk into other buffer ----
        if (more) {
#pragma unroll
            for (int i = 0; i < 4; i++) {
                uint32_t h0, l0, h1, l1;
                split2(av[i].x, av[i].y, h0, l0); split2(av[i].z, av[i].w, h1, l1);
                *(uint32_t*)(nbuf + ao0[i]) = h0;
                *(uint32_t*)(nbuf + ao1[i]) = h1;
                *(uint32_t*)(nbuf + 8192 + ao0[i]) = l0;
                *(uint32_t*)(nbuf + 8192 + ao1[i]) = l1;
                split2(bv[i].x, bv[i].y, h0, l0); split2(bv[i].z, bv[i].w, h1, l1);
                *(uint32_t*)(nbuf + 16384 + bo0[i]) = h0;
                *(uint32_t*)(nbuf + 16384 + bo1[i]) = h1;
                *(uint32_t*)(nbuf + 24576 + bo0[i]) = l0;
                *(uint32_t*)(nbuf + 24576 + bo1[i]) = l1;
            }
            __syncthreads();
        }
    }

    // ---- epilogue ----
    const int g = lane >> 2, t2 = (lane & 3) * 2;
#pragma unroll
    for (int mf = 0; mf < 4; mf++) {
        const int gm = row0 + (wm + mf) * 16 + g;
#pragma unroll
        for (int nf = 0; nf < 4; nf++) {
            const int gn = col0 + (wn + nf) * 8 + t2;
            float c0 = acc[mf][nf][0] * scale, c1 = acc[mf][nf][1] * scale;
            float c2 = acc[mf][nf][2] * scale, c3 = acc[mf][nf][3] * scale;
            if (MODE == 0) {
                *reinterpret_cast<float2*>(&Db[(size_t)gm * ldd + gn]) =
                    make_float2(c0, c1);
                *reinterpret_cast<float2*>(&Db[(size_t)(gm + 8) * ldd + gn]) =
                    make_float2(c2, c3);
            } else {
                Db[(size_t)gn * ldd + gm] = c0;
                Db[(size_t)(gn + 1) * ldd + gm] = c1;
                Db[(size_t)gn * ldd + gm + 8] = c2;
                Db[(size_t)(gn + 1) * ldd + gm + 8] = c3;
            }
        }
    }
}

// ---------------- x transpose: (B,C,N) -> (B,N,C) ----------------
__global__ __launch_bounds__(256) void transpose_x(const float* __restrict__ x,
                                                   float* __restrict__ xt)
{
    __shared__ float t[32][33];
    const int b = blockIdx.z;
    const int n0 = blockIdx.x * 32, c0 = blockIdx.y * 32;
    const int tx = threadIdx.x & 31, ty = threadIdx.x >> 5;
    const float* xb = x + (size_t)b * CCq * NNq;
    float* xtb = xt + (size_t)b * NNq * CCq;
#pragma unroll
    for (int p = 0; p < 4; p++)
        t[ty + p * 8][tx] = xb[(size_t)(c0 + ty + p * 8) * NNq + n0 + tx];
    __syncthreads();
#pragma unroll
    for (int p = 0; p < 4; p++)
        xtb[(size_t)(n0 + ty + p * 8) * CCq + c0 + tx] = t[tx][ty + p * 8];
}

// ---------------- rowwise softmax over 4096 ----------------
__global__ __launch_bounds__(256) void softmax_kernel(float* __restrict__ simp)
{
    float* __restrict__ p = simp + (size_t)blockIdx.x * NNq;
    float4* p4 = reinterpret_cast<float4*>(p);
    const int tid = threadIdx.x;
    __shared__ float sh[8];

    float4 v[4];
#pragma unroll
    for (int j = 0; j < 4; j++) v[j] = p4[tid + 256 * j];

    float mx = -3.4e38f;
#pragma unroll
    for (int j = 0; j < 4; j++)
        mx = fmaxf(mx, fmaxf(fmaxf(v[j].x, v[j].y), fmaxf(v[j].z, v[j].w)));
#pragma unroll
    for (int off = 16; off; off >>= 1)
        mx = fmaxf(mx, __shfl_xor_sync(0xffffffffu, mx, off));
    if ((tid & 31) == 0) sh[tid >> 5] = mx;
    __syncthreads();
    if (tid < 32) {
        float t = (tid < 8) ? sh[tid] : -3.4e38f;
#pragma unroll
        for (int off = 4; off; off >>= 1)
            t = fmaxf(t, __shfl_xor_sync(0xffffffffu, t, off));
        if (tid == 0) sh[0] = t;
    }
    __syncthreads();
    mx = sh[0];
    __syncthreads();

    float s = 0.f;
#pragma unroll
    for (int j = 0; j < 4; j++) {
        v[j].x = __expf(v[j].x - mx);
        v[j].y = __expf(v[j].y - mx);
        v[j].z = __expf(v[j].z - mx);
        v[j].w = __expf(v[j].w - mx);
        s += v[j].x + v[j].y + v[j].z + v[j].w;
    }
#pragma unroll
    for (int off = 16; off; off >>= 1)
        s += __shfl_xor_sync(0xffffffffu, s, off);
    if ((tid & 31) == 0) sh[tid >> 5] = s;
    __syncthreads();
    if (tid < 32) {
        float t = (tid < 8) ? sh[tid] : 0.f;
#pragma unroll
        for (int off = 4; off; off >>= 1)
            t += __shfl_xor_sync(0xffffffffu, t, off);
        if (tid == 0) sh[0] = t;
    }
    __syncthreads();
    const float inv = 1.0f / sh[0];
#pragma unroll
    for (int j = 0; j < 4; j++) {
        v[j].x *= inv; v[j].y *= inv; v[j].z *= inv; v[j].w *= inv;
        p4[tid + 256 * j] = v[j];
    }
}

// ---------------- launch ----------------
extern "C" void kernel_launch(void* const* d_in, const int* in_sizes, int n_in,
                              void* d_out, int out_size)
{
    const float* x  = (const float*)d_in[0];
    const float* Wq = (const float*)d_in[1];
    const float* Wk = (const float*)d_in[2];
    const float* Wv = (const float*)d_in[3];
    const float* Wo = (const float*)d_in[4];
    float* out = (float*)d_out;

    void *xt, *q, *k, *vt, *ctx, *sim;
    cudaGetSymbolAddress(&xt, g_xt);
    cudaGetSymbolAddress(&q, g_q);
    cudaGetSymbolAddress(&k, g_k);
    cudaGetSymbolAddress(&vt, g_vt);
    cudaGetSymbolAddress(&ctx, g_ctx);
    cudaGetSymbolAddress(&sim, g_sim);

    cudaFuncSetAttribute(gemm_bf16x3<0>,
        cudaFuncAttributeMaxDynamicSharedMemorySize, SMEM_TOTAL);
    cudaFuncSetAttribute(gemm_bf16x3<2>,
        cudaFuncAttributeMaxDynamicSharedMemorySize, SMEM_TOTAL);

    const long long sX  = (long long)NNq * CCq;
    const long long sQ  = (long long)NNq * CTq;
    const long long sVT = (long long)CTq * NNq;
    const long long sS  = (long long)NNq * NNq;

    dim3 blk(256);

    // 0) x transpose
    transpose_x<<<dim3(NNq / 32, CCq / 32, BBq), blk>>>(x, (float*)xt);

    // 1) q = xt*Wq^T, k = xt*Wk^T  (rows n, cols o, MODE0)
    gemm_bf16x3<0><<<dim3(32, 2, BBq), blk, SMEM_TOTAL>>>(
        (const float*)xt, CCq, sX, nullptr, 0, 0, CCq,
        Wq, CCq, 0, (float*)q, CTq, sQ, CCq, 1.0f);
    gemm_bf16x3<0><<<dim3(32, 2, BBq), blk, SMEM_TOTAL>>>(
        (const float*)xt, CCq, sX, nullptr, 0, 0, CCq,
        Wk, CCq, 0, (float*)k, CTq, sQ, CCq, 1.0f);
    // v stored transposed -> g_vt (CT,N)
    gemm_bf16x3<2><<<dim3(32, 2, BBq), blk, SMEM_TOTAL>>>(
        (const float*)xt, CCq, sX, nullptr, 0, 0, CCq,
        Wv, CCq, 0, (float*)vt, NNq, sVT, CCq, 1.0f);

    // 2) sim = (q * k^T) / 16
    gemm_bf16x3<0><<<dim3(32, 32, BBq), blk, SMEM_TOTAL>>>(
        (const float*)q, CTq, sQ, nullptr, 0, 0, CTq,
        (const float*)k, CTq, sQ, (float*)sim, NNq, sS, CTq, 0.0625f);

    // 3) softmax rows
    softmax_kernel<<<dim3(BBq * NNq), blk>>>((float*)sim);

    // 4) ctx[n][c] = sum_m P[n][m] * vt[c][m]
    gemm_bf16x3<0><<<dim3(32, 2, BBq), blk, SMEM_TOTAL>>>(
        (const float*)sim, NNq, sS, nullptr, 0, 0, (int)NNq,
        (const float*)vt, NNq, sVT, (float*)ctx, CTq, sQ, NNq, 1.0f);

    // 5) out[o][n]: A = concat(ctx, xt) over K=512, B = Wo, transposed store
    gemm_bf16x3<2><<<dim3(32, 2, BBq), blk, SMEM_TOTAL>>>(
        (const float*)ctx, CTq, sQ, (const float*)xt, CCq, sX, CTq,
        Wo, 2 * CTq, 0, out, NNq, (long long)CCq * NNq, 2 * CTq, 1.0f);
}

// round 6
// speedup vs baseline: 2.4042x; 1.1181x over previous
#include <cuda_runtime.h>
#include <cuda_bf16.h>
#include <cstdint>

#define BBq 4
#define CCq 256
#define NNq 4096
#define CTq 256

typedef __nv_bfloat16 bf16;
typedef __nv_bfloat162 bf162;

// ---------------- persistent bf16 hi/lo planes (device globals) ----------------
__device__ __align__(256) bf16 g_xth[(size_t)BBq * NNq * CCq];
__device__ __align__(256) bf16 g_xtl[(size_t)BBq * NNq * CCq];
__device__ __align__(256) bf16 g_qh [(size_t)BBq * NNq * CTq];
__device__ __align__(256) bf16 g_ql [(size_t)BBq * NNq * CTq];
__device__ __align__(256) bf16 g_kh [(size_t)BBq * NNq * CTq];
__device__ __align__(256) bf16 g_kl [(size_t)BBq * NNq * CTq];
__device__ __align__(256) bf16 g_vth[(size_t)BBq * CTq * NNq];
__device__ __align__(256) bf16 g_vtl[(size_t)BBq * CTq * NNq];
__device__ __align__(256) bf16 g_ch [(size_t)BBq * NNq * CTq];
__device__ __align__(256) bf16 g_cl [(size_t)BBq * NNq * CTq];
__device__ __align__(256) bf16 g_ph [(size_t)BBq * NNq * NNq];
__device__ __align__(256) bf16 g_pl [(size_t)BBq * NNq * NNq];
__device__ __align__(256) bf16 g_wqh[CTq * CCq];
__device__ __align__(256) bf16 g_wql[CTq * CCq];
__device__ __align__(256) bf16 g_wkh[CTq * CCq];
__device__ __align__(256) bf16 g_wkl[CTq * CCq];
__device__ __align__(256) bf16 g_wvh[CTq * CCq];
__device__ __align__(256) bf16 g_wvl[CTq * CCq];
__device__ __align__(256) bf16 g_woh[CCq * 2 * CTq];
__device__ __align__(256) bf16 g_wol[CCq * 2 * CTq];
__device__ __align__(256) float g_sim[(size_t)BBq * NNq * NNq];

// ---------------- helpers ----------------
__device__ __forceinline__ uint32_t smem_u32(const void* p) {
    uint32_t a;
    asm("{ .reg .u64 t; cvta.to.shared.u64 t, %1; cvt.u32.u64 %0, t; }"
        : "=r"(a) : "l"(p));
    return a;
}
#define CP16(dst, src) \
    asm volatile("cp.async.cg.shared.global [%0], [%1], 16;" \
                 :: "r"(dst), "l"(src))
#define CP_COMMIT() asm volatile("cp.async.commit_group;" ::: "memory")
#define CP_WAIT2()  asm volatile("cp.async.wait_group 2;" ::: "memory")

#define LDSM4(r0, r1, r2, r3, addr) \
    asm volatile("ldmatrix.sync.aligned.m8n8.x4.shared.b16 {%0,%1,%2,%3}, [%4];" \
                 : "=r"(r0), "=r"(r1), "=r"(r2), "=r"(r3) : "r"(addr))

__device__ __forceinline__ void mma_bf16(float* d, const uint32_t* a,
                                         const uint32_t* b) {
    asm volatile(
        "mma.sync.aligned.m16n8k16.row.col.f32.bf16.bf16.f32 "
        "{%0,%1,%2,%3}, {%4,%5,%6,%7}, {%8,%9}, {%0,%1,%2,%3};"
        : "+f"(d[0]), "+f"(d[1]), "+f"(d[2]), "+f"(d[3])
        : "r"(a[0]), "r"(a[1]), "r"(a[2]), "r"(a[3]), "r"(b[0]), "r"(b[1]));
}

// ---------------- unified bf16-plane GEMM ----------------
// D[128 x 128] = A[rows,K] * B[cols,K]^T, A/B as bf16 hi/lo planes (K-major).
// Result = AhBh + AhBl + AlBh, fp32 accum.
// OUT=0: fp32 row-major.  OUT=1: bf16 hi/lo row-major.
// OUT=2: fp32 transposed. OUT=3: bf16 hi/lo transposed.
#define STG_BYTES 32768
#define GSMEM (4 * STG_BYTES)

template <int OUT>
__global__ __launch_bounds__(256, 1) void gemm_pl(
    const bf16* __restrict__ A1h, const bf16* __restrict__ A1l, int lda1, long long sA1,
    const bf16* __restrict__ A2h, const bf16* __restrict__ A2l, int lda2, long long sA2,
    int KA1,
    const bf16* __restrict__ Bh, const bf16* __restrict__ Bl, int ldb, long long sB,
    float* __restrict__ Df, bf16* __restrict__ Dh, bf16* __restrict__ Dl,
    int ldd, long long sD, int K, float scale)
{
    extern __shared__ char sm[];
    const uint32_t smb = smem_u32(sm);
    const int tid = threadIdx.x;
    const int wid = tid >> 5, lane = tid & 31;
    const int row0 = blockIdx.x * 128;
    const int col0 = blockIdx.y * 128;
    const int b = blockIdx.z;

    const bf16* __restrict__ A1hb = A1h + (long long)b * sA1;
    const bf16* __restrict__ A1lb = A1l + (long long)b * sA1;
    const bf16* __restrict__ A2hb = A2h ? A2h + (long long)b * sA2 : A1h;
    const bf16* __restrict__ A2lb = A2l ? A2l + (long long)b * sA2 : A1l;
    const bf16* __restrict__ Bhb = Bh + (long long)b * sB + (size_t)col0 * ldb;
    const bf16* __restrict__ Blb = Bl + (long long)b * sB + (size_t)col0 * ldb;

    // staging constants: 2 x 16B chunks per plane per operand
    int sr[2], sc[2];
    uint32_t sdst[2];
#pragma unroll
    for (int i = 0; i < 2; i++) {
        int idx = tid + i * 256;
        sr[i] = idx >> 2;
        sc[i] = idx & 3;
        sdst[i] = sr[i] * 64 + ((sc[i] ^ ((sr[i] >> 1) & 3)) << 4);
    }
    // ldmatrix offsets
    const int lr = lane & 15, lh = lane >> 4;
    uint32_t aoff[4][2], boff[2][2];
#pragma unroll
    for (int mf = 0; mf < 4; mf++)
#pragma unroll
        for (int ks = 0; ks < 2; ks++) {
            int R = (wid & 1) * 64 + mf * 16 + lr;
            int ch = ks * 2 + lh;
            aoff[mf][ks] = R * 64 + ((ch ^ ((R >> 1) & 3)) << 4);
        }
#pragma unroll
    for (int p = 0; p < 2; p++)
#pragma unroll
        for (int ks = 0; ks < 2; ks++) {
            int R = (wid >> 1) * 32 + p * 16 + lr;
            int ch = ks * 2 + lh;
            boff[p][ks] = R * 64 + ((ch ^ ((R >> 1) & 3)) << 4);
        }

    float acc[4][4][4];
#pragma unroll
    for (int mf = 0; mf < 4; mf++)
#pragma unroll
        for (int nf = 0; nf < 4; nf++)
#pragma unroll
            for (int r = 0; r < 4; r++) acc[mf][nf][r] = 0.f;

    const int nch = K / 32;

    auto stage = [&](int c) {
        const int kc = c * 32;
        const bf16 *Ah_, *Al_;
        int lda_, kl = kc;
        if (kc < KA1) { Ah_ = A1hb; Al_ = A1lb; lda_ = lda1; }
        else          { Ah_ = A2hb; Al_ = A2lb; lda_ = lda2; kl = kc - KA1; }
        const uint32_t sb = smb + (uint32_t)(c & 3) * STG_BYTES;
#pragma unroll
        for (int i = 0; i < 2; i++) {
            const int r = sr[i], cc = sc[i];
            const uint32_t d = sdst[i];
            CP16(sb + d,         Ah_ + (size_t)(row0 + r) * lda_ + kl + cc * 8);
            CP16(sb + 8192 + d,  Al_ + (size_t)(row0 + r) * lda_ + kl + cc * 8);
            CP16(sb + 16384 + d, Bhb + (size_t)r * ldb + kc + cc * 8);
            CP16(sb + 24576 + d, Blb + (size_t)r * ldb + kc + cc * 8);
        }
        CP_COMMIT();
    };

    stage(0); stage(1); stage(2);

    for (int c = 0; c < nch; c++) {
        CP_WAIT2();
        __syncthreads();
        const uint32_t sb = smb + (uint32_t)(c & 3) * STG_BYTES;
#pragma unroll
        for (int ks = 0; ks < 2; ks++) {
            uint32_t ah[4][4], al[4][4], bh[4][2], bl[4][2];
#pragma unroll
            for (int mf = 0; mf < 4; mf++) {
                LDSM4(ah[mf][0], ah[mf][1], ah[mf][2], ah[mf][3], sb + aoff[mf][ks]);
                LDSM4(al[mf][0], al[mf][1], al[mf][2], al[mf][3],
                      sb + 8192 + aoff[mf][ks]);
            }
#pragma unroll
            for (int p = 0; p < 2; p++) {
                uint32_t t0, t1, t2, t3;
                LDSM4(t0, t1, t2, t3, sb + 16384 + boff[p][ks]);
                bh[2 * p][0] = t0; bh[2 * p][1] = t2;
                bh[2 * p + 1][0] = t1; bh[2 * p + 1][1] = t3;
                LDSM4(t0, t1, t2, t3, sb + 24576 + boff[p][ks]);
                bl[2 * p][0] = t0; bl[2 * p][1] = t2;
                bl[2 * p + 1][0] = t1; bl[2 * p + 1][1] = t3;
            }
#pragma unroll
            for (int mf = 0; mf < 4; mf++)
#pragma unroll
                for (int nf = 0; nf < 4; nf++) {
                    mma_bf16(acc[mf][nf], ah[mf], bh[nf]);
                    mma_bf16(acc[mf][nf], ah[mf], bl[nf]);
                    mma_bf16(acc[mf][nf], al[mf], bh[nf]);
                }
        }
        if (c + 3 < nch) stage(c + 3);
        else CP_COMMIT();
    }

    // ---------------- epilogue ----------------
    const int g = lane >> 2, t2 = (lane & 3) * 2;
    float* __restrict__ Dfb = Df ? Df + (long long)b * sD : nullptr;
    bf16* __restrict__ Dhb = Dh ? Dh + (long long)b * sD : nullptr;
    bf16* __restrict__ Dlb = Dl ? Dl + (long long)b * sD : nullptr;
#pragma unroll
    for (int mf = 0; mf < 4; mf++) {
        const int gm = row0 + (wid & 1) * 64 + mf * 16 + g;
#pragma unroll
        for (int nf = 0; nf < 4; nf++) {
            const int gn = col0 + (wid >> 1) * 32 + nf * 8 + t2;
            float c0 = acc[mf][nf][0] * scale, c1 = acc[mf][nf][1] * scale;
            float c2 = acc[mf][nf][2] * scale, c3 = acc[mf][nf][3] * scale;
            if (OUT == 0) {
                *reinterpret_cast<float2*>(&Dfb[(size_t)gm * ldd + gn]) =
                    make_float2(c0, c1);
                *reinterpret_cast<float2*>(&Dfb[(size_t)(gm + 8) * ldd + gn]) =
                    make_float2(c2, c3);
            } else if (OUT == 2) {
                Dfb[(size_t)gn * ldd + gm] = c0;
                Dfb[(size_t)(gn + 1) * ldd + gm] = c1;
                Dfb[(size_t)gn * ldd + gm + 8] = c2;
                Dfb[(size_t)(gn + 1) * ldd + gm + 8] = c3;
            } else if (OUT == 1) {
                bf16 h0 = __float2bfloat16(c0), h1 = __float2bfloat16(c1);
                bf16 h2 = __float2bfloat16(c2), h3 = __float2bfloat16(c3);
                bf162 hv0; hv0.x = h0; hv0.y = h1;
                bf162 hv1; hv1.x = h2; hv1.y = h3;
                bf162 lv0; lv0.x = __float2bfloat16(c0 - __bfloat162float(h0));
                lv0.y = __float2bfloat16(c1 - __bfloat162float(h1));
                bf162 lv1; lv1.x = __float2bfloat16(c2 - __bfloat162float(h2));
                lv1.y = __float2bfloat16(c3 - __bfloat162float(h3));
                *reinterpret_cast<bf162*>(&Dhb[(size_t)gm * ldd + gn]) = hv0;
                *reinterpret_cast<bf162*>(&Dhb[(size_t)(gm + 8) * ldd + gn]) = hv1;
                *reinterpret_cast<bf162*>(&Dlb[(size_t)gm * ldd + gn]) = lv0;
                *reinterpret_cast<bf162*>(&Dlb[(size_t)(gm + 8) * ldd + gn]) = lv1;
            } else {  // OUT == 3 transposed bf16 planes
                bf16 h0 = __float2bfloat16(c0), h1 = __float2bfloat16(c1);
                bf16 h2 = __float2bfloat16(c2), h3 = __float2bfloat16(c3);
                Dhb[(size_t)gn * ldd + gm] = h0;
                Dhb[(size_t)(gn + 1) * ldd + gm] = h1;
                Dhb[(size_t)gn * ldd + gm + 8] = h2;
                Dhb[(size_t)(gn + 1) * ldd + gm + 8] = h3;
                Dlb[(size_t)gn * ldd + gm] =
                    __float2bfloat16(c0 - __bfloat162float(h0));
                Dlb[(size_t)(gn + 1) * ldd + gm] =
                    __float2bfloat16(c1 - __bfloat162float(h1));
                Dlb[(size_t)gn * ldd + gm + 8] =
                    __float2bfloat16(c2 - __bfloat162float(h2));
                Dlb[(size_t)(gn + 1) * ldd + gm + 8] =
                    __float2bfloat16(c3 - __bfloat162float(h3));
            }
        }
    }
}

// ---------------- x transpose + split: (B,C,N) fp32 -> (B,N,C) bf16 hi/lo ----
__global__ __launch_bounds__(256) void transpose_split(
    const float* __restrict__ x, bf16* __restrict__ xth, bf16* __restrict__ xtl)
{
    __shared__ float t[32][33];
    const int b = blockIdx.z;
    const int n0 = blockIdx.x * 32, c0 = blockIdx.y * 32;
    const int tx = threadIdx.x & 31, ty = threadIdx.x >> 5;
    const float* xb = x + (size_t)b * CCq * NNq;
    bf16* xh = xth + (size_t)b * NNq * CCq;
    bf16* xl = xtl + (size_t)b * NNq * CCq;
#pragma unroll
    for (int p = 0; p < 4; p++)
        t[ty + p * 8][tx] = xb[(size_t)(c0 + ty + p * 8) * NNq + n0 + tx];
    __syncthreads();
#pragma unroll
    for (int p = 0; p < 4; p++) {
        float v = t[tx][ty + p * 8];
        bf16 h = __float2bfloat16(v);
        xh[(size_t)(n0 + ty + p * 8) * CCq + c0 + tx] = h;
        xl[(size_t)(n0 + ty + p * 8) * CCq + c0 + tx] =
            __float2bfloat16(v - __bfloat162float(h));
    }
}

// ---------------- weight split ----------------
__global__ __launch_bounds__(256) void wsplit(const float* __restrict__ w,
                                              bf16* __restrict__ h,
                                              bf16* __restrict__ l, int n)
{
    int i = blockIdx.x * 256 + threadIdx.x;
    if (i < n) {
        float v = w[i];
        bf16 hh = __float2bfloat16(v);
        h[i] = hh;
        l[i] = __float2bfloat16(v - __bfloat162float(hh));
    }
}

// ---------------- softmax: fp32 sim rows -> P hi/lo bf16 planes ----------------
__global__ __launch_bounds__(256) void softmax_split(
    const float* __restrict__ simp, bf16* __restrict__ ph, bf16* __restrict__ pl)
{
    const float4* p4 = reinterpret_cast<const float4*>(
        simp + (size_t)blockIdx.x * NNq);
    bf162* h2 = reinterpret_cast<bf162*>(ph + (size_t)blockIdx.x * NNq);
    bf162* l2 = reinterpret_cast<bf162*>(pl + (size_t)blockIdx.x * NNq);
    const int tid = threadIdx.x;
    __shared__ float sh[8];

    float4 v[4];
#pragma unroll
    for (int j = 0; j < 4; j++) v[j] = p4[tid + 256 * j];

    float mx = -3.4e38f;
#pragma unroll
    for (int j = 0; j < 4; j++)
        mx = fmaxf(mx, fmaxf(fmaxf(v[j].x, v[j].y), fmaxf(v[j].z, v[j].w)));
#pragma unroll
    for (int off = 16; off; off >>= 1)
        mx = fmaxf(mx, __shfl_xor_sync(0xffffffffu, mx, off));
    if ((tid & 31) == 0) sh[tid >> 5] = mx;
    __syncthreads();
    if (tid < 32) {
        float t = (tid < 8) ? sh[tid] : -3.4e38f;
#pragma unroll
        for (int off = 4; off; off >>= 1)
            t = fmaxf(t, __shfl_xor_sync(0xffffffffu, t, off));
        if (tid == 0) sh[0] = t;
    }
    __syncthreads();
    mx = sh[0];
    __syncthreads();

    float s = 0.f;
#pragma unroll
    for (int j = 0; j < 4; j++) {
        v[j].x = __expf(v[j].x - mx);
        v[j].y = __expf(v[j].y - mx);
        v[j].z = __expf(v[j].z - mx);
        v[j].w = __expf(v[j].w - mx);
        s += v[j].x + v[j].y + v[j].z + v[j].w;
    }
#pragma unroll
    for (int off = 16; off; off >>= 1)
        s += __shfl_xor_sync(0xffffffffu, s, off);
    if ((tid & 31) == 0) sh[tid >> 5] = s;
    __syncthreads();
    if (tid < 32) {
        float t = (tid < 8) ? sh[tid] : 0.f;
#pragma unroll
        for (int off = 4; off; off >>= 1)
            t += __shfl_xor_sync(0xffffffffu, t, off);
        if (tid == 0) sh[0] = t;
    }
    __syncthreads();
    const float inv = 1.0f / sh[0];
#pragma unroll
    for (int j = 0; j < 4; j++) {
        float p0 = v[j].x * inv, p1 = v[j].y * inv;
        float p2 = v[j].z * inv, p3 = v[j].w * inv;
        bf16 h0 = __float2bfloat16(p0), h1 = __float2bfloat16(p1);
        bf16 h2v = __float2bfloat16(p2), h3 = __float2bfloat16(p3);
        bf162 a; a.x = h0; a.y = h1;
        bf162 c; c.x = h2v; c.y = h3;
        bf162 al; al.x = __float2bfloat16(p0 - __bfloat162float(h0));
        al.y = __float2bfloat16(p1 - __bfloat162float(h1));
        bf162 cl; cl.x = __float2bfloat16(p2 - __bfloat162float(h2v));
        cl.y = __float2bfloat16(p3 - __bfloat162float(h3));
        h2[(tid + 256 * j) * 2] = a;
        h2[(tid + 256 * j) * 2 + 1] = c;
        l2[(tid + 256 * j) * 2] = al;
        l2[(tid + 256 * j) * 2 + 1] = cl;
    }
}

// ---------------- launch ----------------
extern "C" void kernel_launch(void* const* d_in, const int* in_sizes, int n_in,
                              void* d_out, int out_size)
{
    const float* x  = (const float*)d_in[0];
    const float* Wq = (const float*)d_in[1];
    const float* Wk = (const float*)d_in[2];
    const float* Wv = (const float*)d_in[3];
    const float* Wo = (const float*)d_in[4];
    float* out = (float*)d_out;

    void *xth, *xtl, *qh, *ql, *kh, *kl, *vth, *vtl, *ch, *cl, *ph, *pl, *sim;
    void *wqh, *wql, *wkh, *wkl, *wvh, *wvl, *woh, *wol;
    cudaGetSymbolAddress(&xth, g_xth); cudaGetSymbolAddress(&xtl, g_xtl);
    cudaGetSymbolAddress(&qh, g_qh);   cudaGetSymbolAddress(&ql, g_ql);
    cudaGetSymbolAddress(&kh, g_kh);   cudaGetSymbolAddress(&kl, g_kl);
    cudaGetSymbolAddress(&vth, g_vth); cudaGetSymbolAddress(&vtl, g_vtl);
    cudaGetSymbolAddress(&ch, g_ch);   cudaGetSymbolAddress(&cl, g_cl);
    cudaGetSymbolAddress(&ph, g_ph);   cudaGetSymbolAddress(&pl, g_pl);
    cudaGetSymbolAddress(&sim, g_sim);
    cudaGetSymbolAddress(&wqh, g_wqh); cudaGetSymbolAddress(&wql, g_wql);
    cudaGetSymbolAddress(&wkh, g_wkh); cudaGetSymbolAddress(&wkl, g_wkl);
    cudaGetSymbolAddress(&wvh, g_wvh); cudaGetSymbolAddress(&wvl, g_wvl);
    cudaGetSymbolAddress(&woh, g_woh); cudaGetSymbolAddress(&wol, g_wol);

    cudaFuncSetAttribute(gemm_pl<0>, cudaFuncAttributeMaxDynamicSharedMemorySize, GSMEM);
    cudaFuncSetAttribute(gemm_pl<1>, cudaFuncAttributeMaxDynamicSharedMemorySize, GSMEM);
    cudaFuncSetAttribute(gemm_pl<2>, cudaFuncAttributeMaxDynamicSharedMemorySize, GSMEM);
    cudaFuncSetAttribute(gemm_pl<3>, cudaFuncAttributeMaxDynamicSharedMemorySize, GSMEM);

    const long long sX  = (long long)NNq * CCq;
    const long long sQ  = (long long)NNq * CTq;
    const long long sVT = (long long)CTq * NNq;
    const long long sS  = (long long)NNq * NNq;
    dim3 blk(256);

    // 0) transpose+split x; split weights
    transpose_split<<<dim3(NNq / 32, CCq / 32, BBq), blk>>>(
        x, (bf16*)xth, (bf16*)xtl);
    wsplit<<<dim3(CTq * CCq / 256), blk>>>(Wq, (bf16*)wqh, (bf16*)wql, CTq * CCq);
    wsplit<<<dim3(CTq * CCq / 256), blk>>>(Wk, (bf16*)wkh, (bf16*)wkl, CTq * CCq);
    wsplit<<<dim3(CTq * CCq / 256), blk>>>(Wv, (bf16*)wvh, (bf16*)wvl, CTq * CCq);
    wsplit<<<dim3(CCq * 2 * CTq / 256), blk>>>(Wo, (bf16*)woh, (bf16*)wol,
                                               CCq * 2 * CTq);

    // 1) q, k (bf16 hi/lo row-major), vt (bf16 hi/lo transposed)
    gemm_pl<1><<<dim3(32, 2, BBq), blk, GSMEM>>>(
        (bf16*)xth, (bf16*)xtl, CCq, sX, nullptr, nullptr, 0, 0, CCq,
        (bf16*)wqh, (bf16*)wql, CCq, 0,
        nullptr, (bf16*)qh, (bf16*)ql, CTq, sQ, CCq, 1.0f);
    gemm_pl<1><<<dim3(32, 2, BBq), blk, GSMEM>>>(
        (bf16*)xth, (bf16*)xtl, CCq, sX, nullptr, nullptr, 0, 0, CCq,
        (bf16*)wkh, (bf16*)wkl, CCq, 0,
        nullptr, (bf16*)kh, (bf16*)kl, CTq, sQ, CCq, 1.0f);
    gemm_pl<3><<<dim3(32, 2, BBq), blk, GSMEM>>>(
        (bf16*)xth, (bf16*)xtl, CCq, sX, nullptr, nullptr, 0, 0, CCq,
        (bf16*)wvh, (bf16*)wvl, CCq, 0,
        nullptr, (bf16*)vth, (bf16*)vtl, NNq, sVT, CCq, 1.0f);

    // 2) sim = (q k^T) / 16, fp32
    gemm_pl<0><<<dim3(32, 32, BBq), blk, GSMEM>>>(
        (bf16*)qh, (bf16*)ql, CTq, sQ, nullptr, nullptr, 0, 0, CTq,
        (bf16*)kh, (bf16*)kl, CTq, sQ,
        (float*)sim, nullptr, nullptr, NNq, sS, CTq, 0.0625f);

    // 3) softmax -> P hi/lo planes
    softmax_split<<<dim3(BBq * NNq), blk>>>((float*)sim, (bf16*)ph, (bf16*)pl);

    // 4) ctx = P * v  (bf16 hi/lo row-major (N,CT))
    gemm_pl<1><<<dim3(32, 2, BBq), blk, GSMEM>>>(
        (bf16*)ph, (bf16*)pl, NNq, sS, nullptr, nullptr, 0, 0, NNq,
        (bf16*)vth, (bf16*)vtl, NNq, sVT,
        nullptr, (bf16*)ch, (bf16*)cl, CTq, sQ, NNq, 1.0f);

    // 5) out = Wo * [ctx; x]  (fp32 transposed store into (B,C,N))
    gemm_pl<2><<<dim3(32, 2, BBq), blk, GSMEM>>>(
        (bf16*)ch, (bf16*)cl, CTq, sQ, (bf16*)xth, (bf16*)xtl, CCq, sX, CTq,
        (bf16*)woh, (bf16*)wol, 2 * CTq, 0,
        out, nullptr, nullptr, NNq, (long long)CCq * NNq, 2 * CTq, 1.0f);
}

// round 7
// speedup vs baseline: 2.4045x; 1.0001x over previous
#include <cuda_runtime.h>
#include <cuda_bf16.h>
#include <cstdint>

#define BBq 4
#define CCq 256
#define NNq 4096
#define CTq 256

typedef __nv_bfloat16 bf16;
typedef __nv_bfloat162 bf162;

// ---------------- persistent bf16 hi/lo planes (device globals) ----------------
__device__ __align__(256) bf16 g_xth[(size_t)BBq * NNq * CCq];
__device__ __align__(256) bf16 g_xtl[(size_t)BBq * NNq * CCq];
__device__ __align__(256) bf16 g_qh [(size_t)BBq * NNq * CTq];
__device__ __align__(256) bf16 g_ql [(size_t)BBq * NNq * CTq];
__device__ __align__(256) bf16 g_kh [(size_t)BBq * NNq * CTq];
__device__ __align__(256) bf16 g_kl [(size_t)BBq * NNq * CTq];
__device__ __align__(256) bf16 g_vth[(size_t)BBq * CTq * NNq];
__device__ __align__(256) bf16 g_vtl[(size_t)BBq * CTq * NNq];
__device__ __align__(256) bf16 g_ch [(size_t)BBq * NNq * CTq];
__device__ __align__(256) bf16 g_cl [(size_t)BBq * NNq * CTq];
__device__ __align__(256) bf16 g_ph [(size_t)BBq * NNq * NNq];
__device__ __align__(256) bf16 g_pl [(size_t)BBq * NNq * NNq];
__device__ __align__(256) bf16 g_wqh[CTq * CCq];
__device__ __align__(256) bf16 g_wql[CTq * CCq];
__device__ __align__(256) bf16 g_wkh[CTq * CCq];
__device__ __align__(256) bf16 g_wkl[CTq * CCq];
__device__ __align__(256) bf16 g_wvh[CTq * CCq];
__device__ __align__(256) bf16 g_wvl[CTq * CCq];
__device__ __align__(256) bf16 g_woh[CCq * 2 * CTq];
__device__ __align__(256) bf16 g_wol[CCq * 2 * CTq];
__device__ __align__(256) float g_sim[(size_t)BBq * NNq * NNq];

// ---------------- helpers ----------------
__device__ __forceinline__ uint32_t smem_u32(const void* p) {
    uint32_t a;
    asm("{ .reg .u64 t; cvta.to.shared.u64 t, %1; cvt.u32.u64 %0, t; }"
        : "=r"(a) : "l"(p));
    return a;
}
#define CP16(dst, src) \
    asm volatile("cp.async.cg.shared.global [%0], [%1], 16;" \
                 :: "r"(dst), "l"(src))
#define CP_COMMIT() asm volatile("cp.async.commit_group;" ::: "memory")
#define CP_WAIT2()  asm volatile("cp.async.wait_group 2;" ::: "memory")

#define LDSM4(r0, r1, r2, r3, addr) \
    asm volatile("ldmatrix.sync.aligned.m8n8.x4.shared.b16 {%0,%1,%2,%3}, [%4];" \
                 : "=r"(r0), "=r"(r1), "=r"(r2), "=r"(r3) : "r"(addr))

__device__ __forceinline__ void mma_bf16(float* d, const uint32_t* a,
                                         const uint32_t* b) {
    asm volatile(
        "mma.sync.aligned.m16n8k16.row.col.f32.bf16.bf16.f32 "
        "{%0,%1,%2,%3}, {%4,%5,%6,%7}, {%8,%9}, {%0,%1,%2,%3};"
        : "+f"(d[0]), "+f"(d[1]), "+f"(d[2]), "+f"(d[3])
        : "r"(a[0]), "r"(a[1]), "r"(a[2]), "r"(a[3]), "r"(b[0]), "r"(b[1]));
}

// ---------------- unified bf16-plane GEMM ----------------
// D[128 x 128] = A[rows,K] * B[cols,K]^T, A/B as bf16 hi/lo planes (K-major).
// Result = AhBh + AhBl + AlBh, fp32 accum.
// OUT=0: fp32 row-major.  OUT=1: bf16 hi/lo row-major.
// OUT=2: fp32 transposed. OUT=3: bf16 hi/lo transposed.
#define STG_BYTES 32768
#define GSMEM (4 * STG_BYTES)

template <int OUT>
__global__ __launch_bounds__(256, 1) void gemm_pl(
    const bf16* __restrict__ A1h, const bf16* __restrict__ A1l, int lda1, long long sA1,
    const bf16* __restrict__ A2h, const bf16* __restrict__ A2l, int lda2, long long sA2,
    int KA1,
    const bf16* __restrict__ Bh, const bf16* __restrict__ Bl, int ldb, long long sB,
    float* __restrict__ Df, bf16* __restrict__ Dh, bf16* __restrict__ Dl,
    int ldd, long long sD, int K, float scale)
{
    extern __shared__ char sm[];
    const uint32_t smb = smem_u32(sm);
    const int tid = threadIdx.x;
    const int wid = tid >> 5, lane = tid & 31;
    const int row0 = blockIdx.x * 128;
    const int col0 = blockIdx.y * 128;
    const int b = blockIdx.z;

    const bf16* __restrict__ A1hb = A1h + (long long)b * sA1;
    const bf16* __restrict__ A1lb = A1l + (long long)b * sA1;
    const bf16* __restrict__ A2hb = A2h ? A2h + (long long)b * sA2 : A1h;
    const bf16* __restrict__ A2lb = A2l ? A2l + (long long)b * sA2 : A1l;
    const bf16* __restrict__ Bhb = Bh + (long long)b * sB + (size_t)col0 * ldb;
    const bf16* __restrict__ Blb = Bl + (long long)b * sB + (size_t)col0 * ldb;

    // staging constants: 2 x 16B chunks per plane per operand
    int sr[2], sc[2];
    uint32_t sdst[2];
#pragma unroll
    for (int i = 0; i < 2; i++) {
        int idx = tid + i * 256;
        sr[i] = idx >> 2;
        sc[i] = idx & 3;
        sdst[i] = sr[i] * 64 + ((sc[i] ^ ((sr[i] >> 1) & 3)) << 4);
    }
    // ldmatrix offsets
    const int lr = lane & 15, lh = lane >> 4;
    uint32_t aoff[4][2], boff[2][2];
#pragma unroll
    for (int mf = 0; mf < 4; mf++)
#pragma unroll
        for (int ks = 0; ks < 2; ks++) {
            int R = (wid & 1) * 64 + mf * 16 + lr;
            int ch = ks * 2 + lh;
            aoff[mf][ks] = R * 64 + ((ch ^ ((R >> 1) & 3)) << 4);
        }
#pragma unroll
    for (int p = 0; p < 2; p++)
#pragma unroll
        for (int ks = 0; ks < 2; ks++) {
            int R = (wid >> 1) * 32 + p * 16 + lr;
            int ch = ks * 2 + lh;
            boff[p][ks] = R * 64 + ((ch ^ ((R >> 1) & 3)) << 4);
        }

    float acc[4][4][4];
#pragma unroll
    for (int mf = 0; mf < 4; mf++)
#pragma unroll
        for (int nf = 0; nf < 4; nf++)
#pragma unroll
            for (int r = 0; r < 4; r++) acc[mf][nf][r] = 0.f;

    const int nch = K / 32;

    auto stage = [&](int c) {
        const int kc = c * 32;
        const bf16 *Ah_, *Al_;
        int lda_, kl = kc;
        if (kc < KA1) { Ah_ = A1hb; Al_ = A1lb; lda_ = lda1; }
        else          { Ah_ = A2hb; Al_ = A2lb; lda_ = lda2; kl = kc - KA1; }
        const uint32_t sb = smb + (uint32_t)(c & 3) * STG_BYTES;
#pragma unroll
        for (int i = 0; i < 2; i++) {
            const int r = sr[i], cc = sc[i];
            const uint32_t d = sdst[i];
            CP16(sb + d,         Ah_ + (size_t)(row0 + r) * lda_ + kl + cc * 8);
            CP16(sb + 8192 + d,  Al_ + (size_t)(row0 + r) * lda_ + kl + cc * 8);
            CP16(sb + 16384 + d, Bhb + (size_t)r * ldb + kc + cc * 8);
            CP16(sb + 24576 + d, Blb + (size_t)r * ldb + kc + cc * 8);
        }
        CP_COMMIT();
    };

    stage(0); stage(1); stage(2);

    for (int c = 0; c < nch; c++) {
        CP_WAIT2();
        __syncthreads();
        const uint32_t sb = smb + (uint32_t)(c & 3) * STG_BYTES;
#pragma unroll
        for (int ks = 0; ks < 2; ks++) {
            uint32_t ah[4][4], al[4][4], bh[4][2], bl[4][2];
#pragma unroll
            for (int mf = 0; mf < 4; mf++) {
                LDSM4(ah[mf][0], ah[mf][1], ah[mf][2], ah[mf][3], sb + aoff[mf][ks]);
                LDSM4(al[mf][0], al[mf][1], al[mf][2], al[mf][3],
                      sb + 8192 + aoff[mf][ks]);
            }
#pragma unroll
            for (int p = 0; p < 2; p++) {
                uint32_t t0, t1, t2, t3;
                LDSM4(t0, t1, t2, t3, sb + 16384 + boff[p][ks]);
                bh[2 * p][0] = t0; bh[2 * p][1] = t2;
                bh[2 * p + 1][0] = t1; bh[2 * p + 1][1] = t3;
                LDSM4(t0, t1, t2, t3, sb + 24576 + boff[p][ks]);
                bl[2 * p][0] = t0; bl[2 * p][1] = t2;
                bl[2 * p + 1][0] = t1; bl[2 * p + 1][1] = t3;
            }
#pragma unroll
            for (int mf = 0; mf < 4; mf++)
#pragma unroll
                for (int nf = 0; nf < 4; nf++) {
                    mma_bf16(acc[mf][nf], ah[mf], bh[nf]);
                    mma_bf16(acc[mf][nf], ah[mf], bl[nf]);
                    mma_bf16(acc[mf][nf], al[mf], bh[nf]);
                }
        }
        if (c + 3 < nch) stage(c + 3);
        else CP_COMMIT();
    }

    // ---------------- epilogue ----------------
    const int g = lane >> 2, t2 = (lane & 3) * 2;
    float* __restrict__ Dfb = Df ? Df + (long long)b * sD : nullptr;
    bf16* __restrict__ Dhb = Dh ? Dh + (long long)b * sD : nullptr;
    bf16* __restrict__ Dlb = Dl ? Dl + (long long)b * sD : nullptr;
#pragma unroll
    for (int mf = 0; mf < 4; mf++) {
        const int gm = row0 + (wid & 1) * 64 + mf * 16 + g;
#pragma unroll
        for (int nf = 0; nf < 4; nf++) {
            const int gn = col0 + (wid >> 1) * 32 + nf * 8 + t2;
            float c0 = acc[mf][nf][0] * scale, c1 = acc[mf][nf][1] * scale;
            float c2 = acc[mf][nf][2] * scale, c3 = acc[mf][nf][3] * scale;
            if (OUT == 0) {
                *reinterpret_cast<float2*>(&Dfb[(size_t)gm * ldd + gn]) =
                    make_float2(c0, c1);
                *reinterpret_cast<float2*>(&Dfb[(size_t)(gm + 8) * ldd + gn]) =
                    make_float2(c2, c3);
            } else if (OUT == 2) {
                Dfb[(size_t)gn * ldd + gm] = c0;
                Dfb[(size_t)(gn + 1) * ldd + gm] = c1;
                Dfb[(size_t)gn * ldd + gm + 8] = c2;
                Dfb[(size_t)(gn + 1) * ldd + gm + 8] = c3;
            } else if (OUT == 1) {
                bf16 h0 = __float2bfloat16(c0), h1 = __float2bfloat16(c1);
                bf16 h2 = __float2bfloat16(c2), h3 = __float2bfloat16(c3);
                bf162 hv0; hv0.x = h0; hv0.y = h1;
                bf162 hv1; hv1.x = h2; hv1.y = h3;
                bf162 lv0; lv0.x = __float2bfloat16(c0 - __bfloat162float(h0));
                lv0.y = __float2bfloat16(c1 - __bfloat162float(h1));
                bf162 lv1; lv1.x = __float2bfloat16(c2 - __bfloat162float(h2));
                lv1.y = __float2bfloat16(c3 - __bfloat162float(h3));
                *reinterpret_cast<bf162*>(&Dhb[(size_t)gm * ldd + gn]) = hv0;
                *reinterpret_cast<bf162*>(&Dhb[(size_t)(gm + 8) * ldd + gn]) = hv1;
                *reinterpret_cast<bf162*>(&Dlb[(size_t)gm * ldd + gn]) = lv0;
                *reinterpret_cast<bf162*>(&Dlb[(size_t)(gm + 8) * ldd + gn]) = lv1;
            } else {  // OUT == 3 transposed bf16 planes
                bf16 h0 = __float2bfloat16(c0), h1 = __float2bfloat16(c1);
                bf16 h2 = __float2bfloat16(c2), h3 = __float2bfloat16(c3);
                Dhb[(size_t)gn * ldd + gm] = h0;
                Dhb[(size_t)(gn + 1) * ldd + gm] = h1;
                Dhb[(size_t)gn * ldd + gm + 8] = h2;
                Dhb[(size_t)(gn + 1) * ldd + gm + 8] = h3;
                Dlb[(size_t)gn * ldd + gm] =
                    __float2bfloat16(c0 - __bfloat162float(h0));
                Dlb[(size_t)(gn + 1) * ldd + gm] =
                    __float2bfloat16(c1 - __bfloat162float(h1));
                Dlb[(size_t)gn * ldd + gm + 8] =
                    __float2bfloat16(c2 - __bfloat162float(h2));
                Dlb[(size_t)(gn + 1) * ldd + gm + 8] =
                    __float2bfloat16(c3 - __bfloat162float(h3));
            }
        }
    }
}

// ---------------- x transpose + split: (B,C,N) fp32 -> (B,N,C) bf16 hi/lo ----
__global__ __launch_bounds__(256) void transpose_split(
    const float* __restrict__ x, bf16* __restrict__ xth, bf16* __restrict__ xtl)
{
    __shared__ float t[32][33];
    const int b = blockIdx.z;
    const int n0 = blockIdx.x * 32, c0 = blockIdx.y * 32;
    const int tx = threadIdx.x & 31, ty = threadIdx.x >> 5;
    const float* xb = x + (size_t)b * CCq * NNq;
    bf16* xh = xth + (size_t)b * NNq * CCq;
    bf16* xl = xtl + (size_t)b * NNq * CCq;
#pragma unroll
    for (int p = 0; p < 4; p++)
        t[ty + p * 8][tx] = xb[(size_t)(c0 + ty + p * 8) * NNq + n0 + tx];
    __syncthreads();
#pragma unroll
    for (int p = 0; p < 4; p++) {
        float v = t[tx][ty + p * 8];
        bf16 h = __float2bfloat16(v);
        xh[(size_t)(n0 + ty + p * 8) * CCq + c0 + tx] = h;
        xl[(size_t)(n0 + ty + p * 8) * CCq + c0 + tx] =
            __float2bfloat16(v - __bfloat162float(h));
    }
}

// ---------------- weight split ----------------
__global__ __launch_bounds__(256) void wsplit(const float* __restrict__ w,
                                              bf16* __restrict__ h,
                                              bf16* __restrict__ l, int n)
{
    int i = blockIdx.x * 256 + threadIdx.x;
    if (i < n) {
        float v = w[i];
        bf16 hh = __float2bfloat16(v);
        h[i] = hh;
        l[i] = __float2bfloat16(v - __bfloat162float(hh));
    }
}

// ---------------- softmax: fp32 sim rows -> P hi/lo bf16 planes ----------------
__global__ __launch_bounds__(256) void softmax_split(
    const float* __restrict__ simp, bf16* __restrict__ ph, bf16* __restrict__ pl)
{
    const float4* p4 = reinterpret_cast<const float4*>(
        simp + (size_t)blockIdx.x * NNq);
    bf162* h2 = reinterpret_cast<bf162*>(ph + (size_t)blockIdx.x * NNq);
    bf162* l2 = reinterpret_cast<bf162*>(pl + (size_t)blockIdx.x * NNq);
    const int tid = threadIdx.x;
    __shared__ float sh[8];

    float4 v[4];
#pragma unroll
    for (int j = 0; j < 4; j++) v[j] = p4[tid + 256 * j];

    float mx = -3.4e38f;
#pragma unroll
    for (int j = 0; j < 4; j++)
        mx = fmaxf(mx, fmaxf(fmaxf(v[j].x, v[j].y), fmaxf(v[j].z, v[j].w)));
#pragma unroll
    for (int off = 16; off; off >>= 1)
        mx = fmaxf(mx, __shfl_xor_sync(0xffffffffu, mx, off));
    if ((tid & 31) == 0) sh[tid >> 5] = mx;
    __syncthreads();
    if (tid < 32) {
        float t = (tid < 8) ? sh[tid] : -3.4e38f;
#pragma unroll
        for (int off = 4; off; off >>= 1)
            t = fmaxf(t, __shfl_xor_sync(0xffffffffu, t, off));
        if (tid == 0) sh[0] = t;
    }
    __syncthreads();
    mx = sh[0];
    __syncthreads();

    float s = 0.f;
#pragma unroll
    for (int j = 0; j < 4; j++) {
        v[j].x = __expf(v[j].x - mx);
        v[j].y = __expf(v[j].y - mx);
        v[j].z = __expf(v[j].z - mx);
        v[j].w = __expf(v[j].w - mx);
        s += v[j].x + v[j].y + v[j].z + v[j].w;
    }
#pragma unroll
    for (int off = 16; off; off >>= 1)
        s += __shfl_xor_sync(0xffffffffu, s, off);
    if ((tid & 31) == 0) sh[tid >> 5] = s;
    __syncthreads();
    if (tid < 32) {
        float t = (tid < 8) ? sh[tid] : 0.f;
#pragma unroll
        for (int off = 4; off; off >>= 1)
            t += __shfl_xor_sync(0xffffffffu, t, off);
        if (tid == 0) sh[0] = t;
    }
    __syncthreads();
    const float inv = 1.0f / sh[0];
#pragma unroll
    for (int j = 0; j < 4; j++) {
        float p0 = v[j].x * inv, p1 = v[j].y * inv;
        float p2 = v[j].z * inv, p3 = v[j].w * inv;
        bf16 h0 = __float2bfloat16(p0), h1 = __float2bfloat16(p1);
        bf16 h2v = __float2bfloat16(p2), h3 = __float2bfloat16(p3);
        bf162 a; a.x = h0; a.y = h1;
        bf162 c; c.x = h2v; c.y = h3;
        bf162 al; al.x = __float2bfloat16(p0 - __bfloat162float(h0));
        al.y = __float2bfloat16(p1 - __bfloat162float(h1));
        bf162 cl; cl.x = __float2bfloat16(p2 - __bfloat162float(h2v));
        cl.y = __float2bfloat16(p3 - __bfloat162float(h3));
        h2[(tid + 256 * j) * 2] = a;
        h2[(tid + 256 * j) * 2 + 1] = c;
        l2[(tid + 256 * j) * 2] = al;
        l2[(tid + 256 * j) * 2 + 1] = cl;
    }
}

// ---------------- launch ----------------
extern "C" void kernel_launch(void* const* d_in, const int* in_sizes, int n_in,
                              void* d_out, int out_size)
{
    const float* x  = (const float*)d_in[0];
    const float* Wq = (const float*)d_in[1];
    const float* Wk = (const float*)d_in[2];
    const float* Wv = (const float*)d_in[3];
    const float* Wo = (const float*)d_in[4];
    float* out = (float*)d_out;

    void *xth, *xtl, *qh, *ql, *kh, *kl, *vth, *vtl, *ch, *cl, *ph, *pl, *sim;
    void *wqh, *wql, *wkh, *wkl, *wvh, *wvl, *woh, *wol;
    cudaGetSymbolAddress(&xth, g_xth); cudaGetSymbolAddress(&xtl, g_xtl);
    cudaGetSymbolAddress(&qh, g_qh);   cudaGetSymbolAddress(&ql, g_ql);
    cudaGetSymbolAddress(&kh, g_kh);   cudaGetSymbolAddress(&kl, g_kl);
    cudaGetSymbolAddress(&vth, g_vth); cudaGetSymbolAddress(&vtl, g_vtl);
    cudaGetSymbolAddress(&ch, g_ch);   cudaGetSymbolAddress(&cl, g_cl);
    cudaGetSymbolAddress(&ph, g_ph);   cudaGetSymbolAddress(&pl, g_pl);
    cudaGetSymbolAddress(&sim, g_sim);
    cudaGetSymbolAddress(&wqh, g_wqh); cudaGetSymbolAddress(&wql, g_wql);
    cudaGetSymbolAddress(&wkh, g_wkh); cudaGetSymbolAddress(&wkl, g_wkl);
    cudaGetSymbolAddress(&wvh, g_wvh); cudaGetSymbolAddress(&wvl, g_wvl);
    cudaGetSymbolAddress(&woh, g_woh); cudaGetSymbolAddress(&wol, g_wol);

    cudaFuncSetAttribute(gemm_pl<0>, cudaFuncAttributeMaxDynamicSharedMemorySize, GSMEM);
    cudaFuncSetAttribute(gemm_pl<1>, cudaFuncAttributeMaxDynamicSharedMemorySize, GSMEM);
    cudaFuncSetAttribute(gemm_pl<2>, cudaFuncAttributeMaxDynamicSharedMemorySize, GSMEM);
    cudaFuncSetAttribute(gemm_pl<3>, cudaFuncAttributeMaxDynamicSharedMemorySize, GSMEM);

    const long long sX  = (long long)NNq * CCq;
    const long long sQ  = (long long)NNq * CTq;
    const long long sVT = (long long)CTq * NNq;
    const long long sS  = (long long)NNq * NNq;
    dim3 blk(256);

    // 0) transpose+split x; split weights
    transpose_split<<<dim3(NNq / 32, CCq / 32, BBq), blk>>>(
        x, (bf16*)xth, (bf16*)xtl);
    wsplit<<<dim3(CTq * CCq / 256), blk>>>(Wq, (bf16*)wqh, (bf16*)wql, CTq * CCq);
    wsplit<<<dim3(CTq * CCq / 256), blk>>>(Wk, (bf16*)wkh, (bf16*)wkl, CTq * CCq);
    wsplit<<<dim3(CTq * CCq / 256), blk>>>(Wv, (bf16*)wvh, (bf16*)wvl, CTq * CCq);
    wsplit<<<dim3(CCq * 2 * CTq / 256), blk>>>(Wo, (bf16*)woh, (bf16*)wol,
                                               CCq * 2 * CTq);

    // 1) q, k (bf16 hi/lo row-major), vt (bf16 hi/lo transposed)
    gemm_pl<1><<<dim3(32, 2, BBq), blk, GSMEM>>>(
        (bf16*)xth, (bf16*)xtl, CCq, sX, nullptr, nullptr, 0, 0, CCq,
        (bf16*)wqh, (bf16*)wql, CCq, 0,
        nullptr, (bf16*)qh, (bf16*)ql, CTq, sQ, CCq, 1.0f);
    gemm_pl<1><<<dim3(32, 2, BBq), blk, GSMEM>>>(
        (bf16*)xth, (bf16*)xtl, CCq, sX, nullptr, nullptr, 0, 0, CCq,
        (bf16*)wkh, (bf16*)wkl, CCq, 0,
        nullptr, (bf16*)kh, (bf16*)kl, CTq, sQ, CCq, 1.0f);
    gemm_pl<3><<<dim3(32, 2, BBq), blk, GSMEM>>>(
        (bf16*)xth, (bf16*)xtl, CCq, sX, nullptr, nullptr, 0, 0, CCq,
        (bf16*)wvh, (bf16*)wvl, CCq, 0,
        nullptr, (bf16*)vth, (bf16*)vtl, NNq, sVT, CCq, 1.0f);

    // 2) sim = (q k^T) / 16, fp32
    gemm_pl<0><<<dim3(32, 32, BBq), blk, GSMEM>>>(
        (bf16*)qh, (bf16*)ql, CTq, sQ, nullptr, nullptr, 0, 0, CTq,
        (bf16*)kh, (bf16*)kl, CTq, sQ,
        (float*)sim, nullptr, nullptr, NNq, sS, CTq, 0.0625f);

    // 3) softmax -> P hi/lo planes
    softmax_split<<<dim3(BBq * NNq), blk>>>((float*)sim, (bf16*)ph, (bf16*)pl);

    // 4) ctx = P * v  (bf16 hi/lo row-major (N,CT))
    gemm_pl<1><<<dim3(32, 2, BBq), blk, GSMEM>>>(
        (bf16*)ph, (bf16*)pl, NNq, sS, nullptr, nullptr, 0, 0, NNq,
        (bf16*)vth, (bf16*)vtl, NNq, sVT,
        nullptr, (bf16*)ch, (bf16*)cl, CTq, sQ, NNq, 1.0f);

    // 5) out = Wo * [ctx; x]  (fp32 transposed store into (B,C,N))
    gemm_pl<2><<<dim3(32, 2, BBq), blk, GSMEM>>>(
        (bf16*)ch, (bf16*)cl, CTq, sQ, (bf16*)xth, (bf16*)xtl, CCq, sX, CTq,
        (bf16*)woh, (bf16*)wol, 2 * CTq, 0,
        out, nullptr, nullptr, NNq, (long long)CCq * NNq, 2 * CTq, 1.0f);
}

// round 8
// speedup vs baseline: 5.1724x; 2.1512x over previous
#include <cuda_runtime.h>
#include <cuda_bf16.h>
#include <cuda_fp16.h>
#include <cstdint>

#define BBq 4
#define CCq 256
#define NNq 4096
#define CTq 256

typedef __nv_bfloat16 bf16;
typedef __nv_bfloat162 bf162;

// ---------------- persistent planes (device globals) ----------------
__device__ __align__(256) bf16   g_xth[(size_t)BBq * NNq * CCq];
__device__ __align__(256) bf16   g_xtl[(size_t)BBq * NNq * CCq];
__device__ __align__(256) __half g_qf [(size_t)BBq * NNq * CTq];
__device__ __align__(256) __half g_kf [(size_t)BBq * NNq * CTq];
__device__ __align__(256) __half g_vf [(size_t)BBq * NNq * CTq];
__device__ __align__(256) bf16   g_ch [(size_t)BBq * NNq * CTq];
__device__ __align__(256) bf16   g_cl [(size_t)BBq * NNq * CTq];
__device__ __align__(256) bf16   g_wqh[CTq * CCq];
__device__ __align__(256) bf16   g_wql[CTq * CCq];
__device__ __align__(256) bf16   g_wkh[CTq * CCq];
__device__ __align__(256) bf16   g_wkl[CTq * CCq];
__device__ __align__(256) bf16   g_wvh[CTq * CCq];
__device__ __align__(256) bf16   g_wvl[CTq * CCq];
__device__ __align__(256) bf16   g_woh[CCq * 2 * CTq];
__device__ __align__(256) bf16   g_wol[CCq * 2 * CTq];

// ---------------- helpers ----------------
__device__ __forceinline__ uint32_t smem_u32(const void* p) {
    uint32_t a;
    asm("{ .reg .u64 t; cvta.to.shared.u64 t, %1; cvt.u32.u64 %0, t; }"
        : "=r"(a) : "l"(p));
    return a;
}
#define CP16(dst, src) \
    asm volatile("cp.async.cg.shared.global [%0], [%1], 16;" \
                 :: "r"(dst), "l"(src))
#define CP_COMMIT() asm volatile("cp.async.commit_group;" ::: "memory")

#define LDSM4(r0, r1, r2, r3, addr) \
    asm volatile("ldmatrix.sync.aligned.m8n8.x4.shared.b16 {%0,%1,%2,%3}, [%4];" \
                 : "=r"(r0), "=r"(r1), "=r"(r2), "=r"(r3) : "r"(addr))
#define LDSM4T(r0, r1, r2, r3, addr) \
    asm volatile("ldmatrix.sync.aligned.m8n8.x4.trans.shared.b16 {%0,%1,%2,%3}, [%4];" \
                 : "=r"(r0), "=r"(r1), "=r"(r2), "=r"(r3) : "r"(addr))

__device__ __forceinline__ void mma_bf16(float* d, const uint32_t* a,
                                         const uint32_t* b) {
    asm volatile(
        "mma.sync.aligned.m16n8k16.row.col.f32.bf16.bf16.f32 "
        "{%0,%1,%2,%3}, {%4,%5,%6,%7}, {%8,%9}, {%0,%1,%2,%3};"
        : "+f"(d[0]), "+f"(d[1]), "+f"(d[2]), "+f"(d[3])
        : "r"(a[0]), "r"(a[1]), "r"(a[2]), "r"(a[3]), "r"(b[0]), "r"(b[1]));
}
__device__ __forceinline__ void mma_f16(float* d, const uint32_t* a,
                                        uint32_t b0, uint32_t b1) {
    asm volatile(
        "mma.sync.aligned.m16n8k16.row.col.f32.f16.f16.f32 "
        "{%0,%1,%2,%3}, {%4,%5,%6,%7}, {%8,%9}, {%0,%1,%2,%3};"
        : "+f"(d[0]), "+f"(d[1]), "+f"(d[2]), "+f"(d[3])
        : "r"(a[0]), "r"(a[1]), "r"(a[2]), "r"(a[3]), "r"(b0), "r"(b1));
}
__device__ __forceinline__ uint32_t pack_h2(float a, float b) {
    __half2 h = __floats2half2_rn(a, b);
    return *reinterpret_cast<uint32_t*>(&h);
}

// ---------------- bf16-plane 3-term GEMM (validated in R6) ----------------
// D[128x128] = A[rows,K] * B[cols,K]^T; A/B bf16 hi/lo planes, K-major.
// OUT=2: fp32 transposed store.   OUT=4: fp16 row-major store (ldd/sD in halves).
#define STG_BYTES 32768
#define GSMEM (4 * STG_BYTES)

template <int OUT>
__global__ __launch_bounds__(256, 1) void gemm_pl(
    const bf16* __restrict__ A1h, const bf16* __restrict__ A1l, int lda1, long long sA1,
    const bf16* __restrict__ A2h, const bf16* __restrict__ A2l, int lda2, long long sA2,
    int KA1,
    const bf16* __restrict__ Bh, const bf16* __restrict__ Bl, int ldb, long long sB,
    void* __restrict__ Dp, int ldd, long long sD, int K, float scale)
{
    extern __shared__ char sm[];
    const uint32_t smb = smem_u32(sm);
    const int tid = threadIdx.x;
    const int wid = tid >> 5, lane = tid & 31;
    const int row0 = blockIdx.x * 128;
    const int col0 = blockIdx.y * 128;
    const int b = blockIdx.z;

    const bf16* __restrict__ A1hb = A1h + (long long)b * sA1;
    const bf16* __restrict__ A1lb = A1l + (long long)b * sA1;
    const bf16* __restrict__ A2hb = A2h ? A2h + (long long)b * sA2 : A1h;
    const bf16* __restrict__ A2lb = A2l ? A2l + (long long)b * sA2 : A1l;
    const bf16* __restrict__ Bhb = Bh + (long long)b * sB + (size_t)col0 * ldb;
    const bf16* __restrict__ Blb = Bl + (long long)b * sB + (size_t)col0 * ldb;

    int sr[2], sc[2];
    uint32_t sdst[2];
#pragma unroll
    for (int i = 0; i < 2; i++) {
        int idx = tid + i * 256;
        sr[i] = idx >> 2;
        sc[i] = idx & 3;
        sdst[i] = sr[i] * 64 + ((sc[i] ^ ((sr[i] >> 1) & 3)) << 4);
    }
    const int lr = lane & 15, lh = lane >> 4;
    uint32_t aoff[4][2], boff[2][2];
#pragma unroll
    for (int mf = 0; mf < 4; mf++)
#pragma unroll
        for (int ks = 0; ks < 2; ks++) {
            int R = (wid & 1) * 64 + mf * 16 + lr;
            int ch = ks * 2 + lh;
            aoff[mf][ks] = R * 64 + ((ch ^ ((R >> 1) & 3)) << 4);
        }
#pragma unroll
    for (int p = 0; p < 2; p++)
#pragma unroll
        for (int ks = 0; ks < 2; ks++) {
            int R = (wid >> 1) * 32 + p * 16 + lr;
            int ch = ks * 2 + lh;
            boff[p][ks] = R * 64 + ((ch ^ ((R >> 1) & 3)) << 4);
        }

    float acc[4][4][4];
#pragma unroll
    for (int mf = 0; mf < 4; mf++)
#pragma unroll
        for (int nf = 0; nf < 4; nf++)
#pragma unroll
            for (int r = 0; r < 4; r++) acc[mf][nf][r] = 0.f;

    const int nch = K / 32;

    auto stage = [&](int c) {
        const int kc = c * 32;
        const bf16 *Ah_, *Al_;
        int lda_, kl = kc;
        if (kc < KA1) { Ah_ = A1hb; Al_ = A1lb; lda_ = lda1; }
        else          { Ah_ = A2hb; Al_ = A2lb; lda_ = lda2; kl = kc - KA1; }
        const uint32_t sb = smb + (uint32_t)(c & 3) * STG_BYTES;
#pragma unroll
        for (int i = 0; i < 2; i++) {
            const int r = sr[i], cc = sc[i];
            const uint32_t d = sdst[i];
            CP16(sb + d,         Ah_ + (size_t)(row0 + r) * lda_ + kl + cc * 8);
            CP16(sb + 8192 + d,  Al_ + (size_t)(row0 + r) * lda_ + kl + cc * 8);
            CP16(sb + 16384 + d, Bhb + (size_t)r * ldb + kc + cc * 8);
            CP16(sb + 24576 + d, Blb + (size_t)r * ldb + kc + cc * 8);
        }
        CP_COMMIT();
    };

    stage(0); stage(1); stage(2);

    for (int c = 0; c < nch; c++) {
        asm volatile("cp.async.wait_group 2;" ::: "memory");
        __syncthreads();
        const uint32_t sb = smb + (uint32_t)(c & 3) * STG_BYTES;
#pragma unroll
        for (int ks = 0; ks < 2; ks++) {
            uint32_t ah[4][4], al[4][4], bh[4][2], bl[4][2];
#pragma unroll
            for (int mf = 0; mf < 4; mf++) {
                LDSM4(ah[mf][0], ah[mf][1], ah[mf][2], ah[mf][3], sb + aoff[mf][ks]);
                LDSM4(al[mf][0], al[mf][1], al[mf][2], al[mf][3],
                      sb + 8192 + aoff[mf][ks]);
            }
#pragma unroll
            for (int p = 0; p < 2; p++) {
                uint32_t t0, t1, t2, t3;
                LDSM4(t0, t1, t2, t3, sb + 16384 + boff[p][ks]);
                bh[2 * p][0] = t0; bh[2 * p][1] = t2;
                bh[2 * p + 1][0] = t1; bh[2 * p + 1][1] = t3;
                LDSM4(t0, t1, t2, t3, sb + 24576 + boff[p][ks]);
                bl[2 * p][0] = t0; bl[2 * p][1] = t2;
                bl[2 * p + 1][0] = t1; bl[2 * p + 1][1] = t3;
            }
#pragma unroll
            for (int mf = 0; mf < 4; mf++)
#pragma unroll
                for (int nf = 0; nf < 4; nf++) {
                    mma_bf16(acc[mf][nf], ah[mf], bh[nf]);
                    mma_bf16(acc[mf][nf], ah[mf], bl[nf]);
                    mma_bf16(acc[mf][nf], al[mf], bh[nf]);
                }
        }
        if (c + 3 < nch) stage(c + 3);
        else CP_COMMIT();
    }

    const int g = lane >> 2, t2 = (lane & 3) * 2;
#pragma unroll
    for (int mf = 0; mf < 4; mf++) {
        const int gm = row0 + (wid & 1) * 64 + mf * 16 + g;
#pragma unroll
        for (int nf = 0; nf < 4; nf++) {
            const int gn = col0 + (wid >> 1) * 32 + nf * 8 + t2;
            float c0 = acc[mf][nf][0] * scale, c1 = acc[mf][nf][1] * scale;
            float c2 = acc[mf][nf][2] * scale, c3 = acc[mf][nf][3] * scale;
            if (OUT == 2) {
                float* Dfb = (float*)Dp + (long long)b * sD;
                Dfb[(size_t)gn * ldd + gm] = c0;
                Dfb[(size_t)(gn + 1) * ldd + gm] = c1;
                Dfb[(size_t)gn * ldd + gm + 8] = c2;
                Dfb[(size_t)(gn + 1) * ldd + gm + 8] = c3;
            } else {  // OUT == 4: fp16 plane row-major
                __half* Dxb = (__half*)Dp + (long long)b * sD;
                __half2 a01 = __floats2half2_rn(c0, c1);
                __half2 a23 = __floats2half2_rn(c2, c3);
                *reinterpret_cast<__half2*>(&Dxb[(size_t)gm * ldd + gn]) = a01;
                *reinterpret_cast<__half2*>(&Dxb[(size_t)(gm + 8) * ldd + gn]) = a23;
            }
        }
    }
}

// ---------------- fused attention (FA2, fp16 single-plane) ----------------
// 128 query rows/CTA, 8 warps x 16 rows. Q resident (64KB); K/V 4-stage
// pipeline (4 x 32KB). Online softmax. ctx written as bf16 hi/lo planes.
#define FM_SMEM 196608

__global__ __launch_bounds__(256, 1) void fmha(
    const __half* __restrict__ qf, const __half* __restrict__ kf,
    const __half* __restrict__ vf,
    bf16* __restrict__ chp, bf16* __restrict__ clp)
{
    extern __shared__ char sm[];
    const uint32_t smb = smem_u32(sm);
    const uint32_t Qs = smb;
    const int tid = threadIdx.x, wid = tid >> 5, lane = tid & 31;
    const int b = blockIdx.z, row0 = blockIdx.x * 128;
    const long long sQ = (long long)NNq * CTq;
    const __half* __restrict__ qb = qf + b * sQ + (long long)row0 * CTq;
    const __half* __restrict__ kb = kf + b * sQ;
    const __half* __restrict__ vb = vf + b * sQ;

    // ---- stage Q: 128 x 256 fp16, panels of 32 ct (4 chunks), swizzled ----
#pragma unroll
    for (int i = 0; i < 16; i++) {
        int idx = tid + i * 256;
        int row = idx >> 5, cc = idx & 31;
        uint32_t dst = Qs + (cc >> 2) * 8192 + row * 64 +
                       (uint32_t)(((cc & 3) ^ ((row >> 1) & 3)) << 4);
        CP16(dst, qb + (size_t)row * 256 + cc * 8);
    }
    CP_COMMIT();

    auto stage = [&](int c) {
        uint32_t sb = smb + 65536 + (uint32_t)(c & 3) * 32768;
        const __half* ks_ = kb + (size_t)c * 32 * 256;
        const __half* vs_ = vb + (size_t)c * 32 * 256;
#pragma unroll
        for (int i = 0; i < 4; i++) {
            int idx = tid + i * 256;
            int row = idx >> 5, cc = idx & 31;
            uint32_t off = (cc >> 2) * 2048 + row * 64 +
                           (uint32_t)(((cc & 3) ^ ((row >> 1) & 3)) << 4);
            CP16(sb + off, ks_ + (size_t)row * 256 + cc * 8);
            CP16(sb + 16384 + off, vs_ + (size_t)row * 256 + cc * 8);
        }
        CP_COMMIT();
    };
    stage(0); stage(1); stage(2);

    float o[32][4];
#pragma unroll
    for (int nt = 0; nt < 32; nt++)
#pragma unroll
        for (int j = 0; j < 4; j++) o[nt][j] = 0.f;
    float m0 = -1e30f, m1 = -1e30f, l0 = 0.f, l1 = 0.f;

    const int lr = lane & 15, lh = lane >> 4;
    const uint32_t qrow = (uint32_t)(wid * 16 + lr);
    const uint32_t qoff = qrow * 64;
    const uint32_t qswz = (qrow >> 1) & 3;
    const uint32_t krA = (uint32_t)lr * 64;        // keys 0..15
    const uint32_t krB = (uint32_t)(16 + lr) * 64; // keys 16..31
    const uint32_t kswz = ((uint32_t)lr >> 1) & 3;

    for (int c = 0; c < 128; c++) {
        asm volatile("cp.async.wait_group 2;" ::: "memory");
        __syncthreads();
        if (c + 3 < 128) stage(c + 3);
        else CP_COMMIT();
        const uint32_t Ks = smb + 65536 + (uint32_t)(c & 3) * 32768;
        const uint32_t Vs = Ks + 16384;

        // ---- S = Q K^T (16 rows x 32 keys per warp) ----
        float s[4][4];
#pragma unroll
        for (int j = 0; j < 4; j++)
#pragma unroll
            for (int r = 0; r < 4; r++) s[j][r] = 0.f;
#pragma unroll
        for (int ks = 0; ks < 16; ks++) {
            const uint32_t ch = (uint32_t)((((ks & 1) * 2 + lh)) ^ 0);
            uint32_t qa0, qa1, qa2, qa3;
            LDSM4(qa0, qa1, qa2, qa3,
                  Qs + (ks >> 1) * 8192 + qoff +
                  (((uint32_t)((ks & 1) * 2 + lh) ^ qswz) << 4));
            uint32_t qa[4] = {qa0, qa1, qa2, qa3};
            const uint32_t kc = ((uint32_t)((ks & 1) * 2 + lh) ^ kswz) << 4;
            const uint32_t kp = (ks >> 1) * 2048;
            uint32_t t0, t1, t2, t3;
            LDSM4(t0, t1, t2, t3, Ks + kp + krA + kc);
            mma_f16(s[0], qa, t0, t2);
            mma_f16(s[1], qa, t1, t3);
            LDSM4(t0, t1, t2, t3, Ks + kp + krB + kc);
            mma_f16(s[2], qa, t0, t2);
            mma_f16(s[3], qa, t1, t3);
            (void)ch;
        }

        // ---- online softmax ----
        float a0 = fmaxf(fmaxf(s[0][0], s[0][1]), fmaxf(s[1][0], s[1][1]));
        float a1 = fmaxf(fmaxf(s[2][0], s[2][1]), fmaxf(s[3][0], s[3][1]));
        float mx0 = fmaxf(a0, a1);
        float b0v = fmaxf(fmaxf(s[0][2], s[0][3]), fmaxf(s[1][2], s[1][3]));
        float b1v = fmaxf(fmaxf(s[2][2], s[2][3]), fmaxf(s[3][2], s[3][3]));
        float mx1 = fmaxf(b0v, b1v);
        mx0 = fmaxf(mx0, __shfl_xor_sync(0xffffffffu, mx0, 1));
        mx0 = fmaxf(mx0, __shfl_xor_sync(0xffffffffu, mx0, 2));
        mx1 = fmaxf(mx1, __shfl_xor_sync(0xffffffffu, mx1, 1));
        mx1 = fmaxf(mx1, __shfl_xor_sync(0xffffffffu, mx1, 2));
        float nm0 = fmaxf(m0, mx0), nm1 = fmaxf(m1, mx1);
        float f0 = __expf(m0 - nm0), f1 = __expf(m1 - nm1);
        m0 = nm0; m1 = nm1;
#pragma unroll
        for (int j = 0; j < 4; j++) {
            s[j][0] = __expf(s[j][0] - nm0);
            s[j][1] = __expf(s[j][1] - nm0);
            s[j][2] = __expf(s[j][2] - nm1);
            s[j][3] = __expf(s[j][3] - nm1);
        }
        float r0 = (s[0][0] + s[0][1]) + (s[1][0] + s[1][1]) +
                   (s[2][0] + s[2][1]) + (s[3][0] + s[3][1]);
        float r1 = (s[0][2] + s[0][3]) + (s[1][2] + s[1][3]) +
                   (s[2][2] + s[2][3]) + (s[3][2] + s[3][3]);
        r0 += __shfl_xor_sync(0xffffffffu, r0, 1);
        r0 += __shfl_xor_sync(0xffffffffu, r0, 2);
        r1 += __shfl_xor_sync(0xffffffffu, r1, 1);
        r1 += __shfl_xor_sync(0xffffffffu, r1, 2);
        l0 = l0 * f0 + r0;
        l1 = l1 * f1 + r1;
        if (__ballot_sync(0xffffffffu, (f0 < 1.f) | (f1 < 1.f))) {
#pragma unroll
            for (int nt = 0; nt < 32; nt++) {
                o[nt][0] *= f0; o[nt][1] *= f0;
                o[nt][2] *= f1; o[nt][3] *= f1;
            }
        }

        // ---- P fragments (C-frag -> A-frag identity) ----
        uint32_t pk[2][4];
#pragma unroll
        for (int h = 0; h < 2; h++) {
            pk[h][0] = pack_h2(s[2 * h][0], s[2 * h][1]);
            pk[h][1] = pack_h2(s[2 * h][2], s[2 * h][3]);
            pk[h][2] = pack_h2(s[2 * h + 1][0], s[2 * h + 1][1]);
            pk[h][3] = pack_h2(s[2 * h + 1][2], s[2 * h + 1][3]);
        }

        // ---- O += P V ----
#pragma unroll
        for (int h = 0; h < 2; h++) {
            const uint32_t vr = (h == 0) ? krA : krB;
#pragma unroll
            for (int g2 = 0; g2 < 16; g2++) {
                uint32_t v0, v1, v2, v3;
                LDSM4T(v0, v1, v2, v3,
                       Vs + (g2 >> 1) * 2048 + vr +
                       (((uint32_t)((g2 & 1) * 2 + lh) ^ kswz) << 4));
                mma_f16(o[2 * g2], pk[h], v0, v1);
                mma_f16(o[2 * g2 + 1], pk[h], v2, v3);
            }
        }
    }
    asm volatile("cp.async.wait_group 0;" ::: "memory");

    // ---- epilogue: normalize, split to bf16 hi/lo, store (N, CT) ----
    const int g = lane >> 2, t2 = (lane & 3) * 2;
    const float i0 = 1.0f / l0, i1 = 1.0f / l1;
    bf16* __restrict__ chb = chp + b * sQ;
    bf16* __restrict__ clb = clp + b * sQ;
    const int gm0 = row0 + wid * 16 + g;
#pragma unroll
    for (int nt = 0; nt < 32; nt++) {
        const int gn = nt * 8 + t2;
        float c0 = o[nt][0] * i0, c1 = o[nt][1] * i0;
        float c2 = o[nt][2] * i1, c3 = o[nt][3] * i1;
        bf16 h0 = __float2bfloat16(c0), h1 = __float2bfloat16(c1);
        bf16 h2 = __float2bfloat16(c2), h3 = __float2bfloat16(c3);
        bf162 hv0; hv0.x = h0; hv0.y = h1;
        bf162 hv1; hv1.x = h2; hv1.y = h3;
        bf162 lv0; lv0.x = __float2bfloat16(c0 - __bfloat162float(h0));
        lv0.y = __float2bfloat16(c1 - __bfloat162float(h1));
        bf162 lv1; lv1.x = __float2bfloat16(c2 - __bfloat162float(h2));
        lv1.y = __float2bfloat16(c3 - __bfloat162float(h3));
        *reinterpret_cast<bf162*>(&chb[(size_t)gm0 * CTq + gn]) = hv0;
        *reinterpret_cast<bf162*>(&chb[(size_t)(gm0 + 8) * CTq + gn]) = hv1;
        *reinterpret_cast<bf162*>(&clb[(size_t)gm0 * CTq + gn]) = lv0;
        *reinterpret_cast<bf162*>(&clb[(size_t)(gm0 + 8) * CTq + gn]) = lv1;
    }
}

// ---------------- x transpose + split ----------------
__global__ __launch_bounds__(256) void transpose_split(
    const float* __restrict__ x, bf16* __restrict__ xth, bf16* __restrict__ xtl)
{
    __shared__ float t[32][33];
    const int b = blockIdx.z;
    const int n0 = blockIdx.x * 32, c0 = blockIdx.y * 32;
    const int tx = threadIdx.x & 31, ty = threadIdx.x >> 5;
    const float* xb = x + (size_t)b * CCq * NNq;
    bf16* xh = xth + (size_t)b * NNq * CCq;
    bf16* xl = xtl + (size_t)b * NNq * CCq;
#pragma unroll
    for (int p = 0; p < 4; p++)
        t[ty + p * 8][tx] = xb[(size_t)(c0 + ty + p * 8) * NNq + n0 + tx];
    __syncthreads();
#pragma unroll
    for (int p = 0; p < 4; p++) {
        float v = t[tx][ty + p * 8];
        bf16 h = __float2bfloat16(v);
        xh[(size_t)(n0 + ty + p * 8) * CCq + c0 + tx] = h;
        xl[(size_t)(n0 + ty + p * 8) * CCq + c0 + tx] =
            __float2bfloat16(v - __bfloat162float(h));
    }
}

__global__ __launch_bounds__(256) void wsplit(const float* __restrict__ w,
                                              bf16* __restrict__ h,
                                              bf16* __restrict__ l, int n)
{
    int i = blockIdx.x * 256 + threadIdx.x;
    if (i < n) {
        float v = w[i];
        bf16 hh = __float2bfloat16(v);
        h[i] = hh;
        l[i] = __float2bfloat16(v - __bfloat162float(hh));
    }
}

// ---------------- launch ----------------
extern "C" void kernel_launch(void* const* d_in, const int* in_sizes, int n_in,
                              void* d_out, int out_size)
{
    const float* x  = (const float*)d_in[0];
    const float* Wq = (const float*)d_in[1];
    const float* Wk = (const float*)d_in[2];
    const float* Wv = (const float*)d_in[3];
    const float* Wo = (const float*)d_in[4];
    float* out = (float*)d_out;

    void *xth, *xtl, *qf, *kf, *vf, *ch, *cl;
    void *wqh, *wql, *wkh, *wkl, *wvh, *wvl, *woh, *wol;
    cudaGetSymbolAddress(&xth, g_xth); cudaGetSymbolAddress(&xtl, g_xtl);
    cudaGetSymbolAddress(&qf, g_qf);   cudaGetSymbolAddress(&kf, g_kf);
    cudaGetSymbolAddress(&vf, g_vf);
    cudaGetSymbolAddress(&ch, g_ch);   cudaGetSymbolAddress(&cl, g_cl);
    cudaGetSymbolAddress(&wqh, g_wqh); cudaGetSymbolAddress(&wql, g_wql);
    cudaGetSymbolAddress(&wkh, g_wkh); cudaGetSymbolAddress(&wkl, g_wkl);
    cudaGetSymbolAddress(&wvh, g_wvh); cudaGetSymbolAddress(&wvl, g_wvl);
    cudaGetSymbolAddress(&woh, g_woh); cudaGetSymbolAddress(&wol, g_wol);

    cudaFuncSetAttribute(gemm_pl<2>, cudaFuncAttributeMaxDynamicSharedMemorySize, GSMEM);
    cudaFuncSetAttribute(gemm_pl<4>, cudaFuncAttributeMaxDynamicSharedMemorySize, GSMEM);
    cudaFuncSetAttribute(fmha, cudaFuncAttributeMaxDynamicSharedMemorySize, FM_SMEM);

    const long long sX = (long long)NNq * CCq;
    const long long sQ = (long long)NNq * CTq;
    dim3 blk(256);

    // 0) transpose+split x; split weights
    transpose_split<<<dim3(NNq / 32, CCq / 32, BBq), blk>>>(
        x, (bf16*)xth, (bf16*)xtl);
    wsplit<<<dim3(CTq * CCq / 256), blk>>>(Wq, (bf16*)wqh, (bf16*)wql, CTq * CCq);
    wsplit<<<dim3(CTq * CCq / 256), blk>>>(Wk, (bf16*)wkh, (bf16*)wkl, CTq * CCq);
    wsplit<<<dim3(CTq * CCq / 256), blk>>>(Wv, (bf16*)wvh, (bf16*)wvl, CTq * CCq);
    wsplit<<<dim3(CCq * 2 * CTq / 256), blk>>>(Wo, (bf16*)woh, (bf16*)wol,
                                               CCq * 2 * CTq);

    // 1) q (pre-scaled 1/16), k, v as fp16 planes (N, CT)
    gemm_pl<4><<<dim3(32, 2, BBq), blk, GSMEM>>>(
        (bf16*)xth, (bf16*)xtl, CCq, sX, nullptr, nullptr, 0, 0, CCq,
        (bf16*)wqh, (bf16*)wql, CCq, 0, qf, CTq, sQ, CCq, 0.0625f);
    gemm_pl<4><<<dim3(32, 2, BBq), blk, GSMEM>>>(
        (bf16*)xth, (bf16*)xtl, CCq, sX, nullptr, nullptr, 0, 0, CCq,
        (bf16*)wkh, (bf16*)wkl, CCq, 0, kf, CTq, sQ, CCq, 1.0f);
    gemm_pl<4><<<dim3(32, 2, BBq), blk, GSMEM>>>(
        (bf16*)xth, (bf16*)xtl, CCq, sX, nullptr, nullptr, 0, 0, CCq,
        (bf16*)wvh, (bf16*)wvl, CCq, 0, vf, CTq, sQ, CCq, 1.0f);

    // 2) fused attention -> ctx bf16 hi/lo planes
    fmha<<<dim3(32, 1, BBq), blk, FM_SMEM>>>(
        (const __half*)qf, (const __half*)kf, (const __half*)vf,
        (bf16*)ch, (bf16*)cl);

    // 3) out = Wo * [ctx; x]  (fp32 transposed store into (B,C,N))
    gemm_pl<2><<<dim3(32, 2, BBq), blk, GSMEM>>>(
        (bf16*)ch, (bf16*)cl, CTq, sQ, (bf16*)xth, (bf16*)xtl, CCq, sX, CTq,
        (bf16*)woh, (bf16*)wol, 2 * CTq, 0,
        out, NNq, (long long)CCq * NNq, 2 * CTq, 1.0f);
}

// round 9
// speedup vs baseline: 5.7045x; 1.1029x over previous
#include <cuda_runtime.h>
#include <cuda_bf16.h>
#include <cuda_fp16.h>
#include <cstdint>

#define BBq 4
#define CCq 256
#define NNq 4096
#define CTq 256

typedef __nv_bfloat16 bf16;
typedef __nv_bfloat162 bf162;

// ---------------- persistent planes (device globals) ----------------
__device__ __align__(256) bf16   g_xth[(size_t)BBq * NNq * CCq];
__device__ __align__(256) bf16   g_xtl[(size_t)BBq * NNq * CCq];
__device__ __align__(256) __half g_qf [(size_t)BBq * NNq * CTq];
__device__ __align__(256) __half g_kf [(size_t)BBq * NNq * CTq];
__device__ __align__(256) __half g_vf [(size_t)BBq * NNq * CTq];
__device__ __align__(256) bf16   g_ch [(size_t)BBq * NNq * CTq];
__device__ __align__(256) bf16   g_cl [(size_t)BBq * NNq * CTq];
__device__ __align__(256) bf16   g_wqh[CTq * CCq];
__device__ __align__(256) bf16   g_wql[CTq * CCq];
__device__ __align__(256) bf16   g_wkh[CTq * CCq];
__device__ __align__(256) bf16   g_wkl[CTq * CCq];
__device__ __align__(256) bf16   g_wvh[CTq * CCq];
__device__ __align__(256) bf16   g_wvl[CTq * CCq];
__device__ __align__(256) bf16   g_woh[CCq * 2 * CTq];
__device__ __align__(256) bf16   g_wol[CCq * 2 * CTq];

// ---------------- helpers ----------------
__device__ __forceinline__ uint32_t smem_u32(const void* p) {
    uint32_t a;
    asm("{ .reg .u64 t; cvta.to.shared.u64 t, %1; cvt.u32.u64 %0, t; }"
        : "=r"(a) : "l"(p));
    return a;
}
#define CP16(dst, src) \
    asm volatile("cp.async.cg.shared.global [%0], [%1], 16;" \
                 :: "r"(dst), "l"(src))
#define CP_COMMIT() asm volatile("cp.async.commit_group;" ::: "memory")

#define LDSM4(r0, r1, r2, r3, addr) \
    asm volatile("ldmatrix.sync.aligned.m8n8.x4.shared.b16 {%0,%1,%2,%3}, [%4];" \
                 : "=r"(r0), "=r"(r1), "=r"(r2), "=r"(r3) : "r"(addr))
#define LDSM4T(r0, r1, r2, r3, addr) \
    asm volatile("ldmatrix.sync.aligned.m8n8.x4.trans.shared.b16 {%0,%1,%2,%3}, [%4];" \
                 : "=r"(r0), "=r"(r1), "=r"(r2), "=r"(r3) : "r"(addr))

__device__ __forceinline__ void mma_bf16(float* d, const uint32_t* a,
                                         const uint32_t* b) {
    asm volatile(
        "mma.sync.aligned.m16n8k16.row.col.f32.bf16.bf16.f32 "
        "{%0,%1,%2,%3}, {%4,%5,%6,%7}, {%8,%9}, {%0,%1,%2,%3};"
        : "+f"(d[0]), "+f"(d[1]), "+f"(d[2]), "+f"(d[3])
        : "r"(a[0]), "r"(a[1]), "r"(a[2]), "r"(a[3]), "r"(b[0]), "r"(b[1]));
}
__device__ __forceinline__ void mma_f16(float* d, const uint32_t* a,
                                        uint32_t b0, uint32_t b1) {
    asm volatile(
        "mma.sync.aligned.m16n8k16.row.col.f32.f16.f16.f32 "
        "{%0,%1,%2,%3}, {%4,%5,%6,%7}, {%8,%9}, {%0,%1,%2,%3};"
        : "+f"(d[0]), "+f"(d[1]), "+f"(d[2]), "+f"(d[3])
        : "r"(a[0]), "r"(a[1]), "r"(a[2]), "r"(a[3]), "r"(b0), "r"(b1));
}
__device__ __forceinline__ uint32_t pack_h2(float a, float b) {
    __half2 h = __floats2half2_rn(a, b);
    return *reinterpret_cast<uint32_t*>(&h);
}
__device__ __forceinline__ uint32_t ex2_h2(uint32_t x) {
    uint32_t r;
    asm("ex2.approx.f16x2 %0, %1;" : "=r"(r) : "r"(x));
    return r;
}

// ---------------- bf16-plane 3-term GEMM (validated R6/R8) ----------------
// OUT=2: fp32 transposed store.  OUT=4: fp16 row-major store.
#define STG_BYTES 32768
#define GSMEM (4 * STG_BYTES)

template <int OUT>
__global__ __launch_bounds__(256, 1) void gemm_pl(
    const bf16* __restrict__ A1h, const bf16* __restrict__ A1l, int lda1, long long sA1,
    const bf16* __restrict__ A2h, const bf16* __restrict__ A2l, int lda2, long long sA2,
    int KA1,
    const bf16* __restrict__ Bh, const bf16* __restrict__ Bl, int ldb, long long sB,
    void* __restrict__ Dp, int ldd, long long sD, int K, float scale)
{
    extern __shared__ char sm[];
    const uint32_t smb = smem_u32(sm);
    const int tid = threadIdx.x;
    const int wid = tid >> 5, lane = tid & 31;
    const int row0 = blockIdx.x * 128;
    const int col0 = blockIdx.y * 128;
    const int b = blockIdx.z;

    const bf16* __restrict__ A1hb = A1h + (long long)b * sA1;
    const bf16* __restrict__ A1lb = A1l + (long long)b * sA1;
    const bf16* __restrict__ A2hb = A2h ? A2h + (long long)b * sA2 : A1h;
    const bf16* __restrict__ A2lb = A2l ? A2l + (long long)b * sA2 : A1l;
    const bf16* __restrict__ Bhb = Bh + (long long)b * sB + (size_t)col0 * ldb;
    const bf16* __restrict__ Blb = Bl + (long long)b * sB + (size_t)col0 * ldb;

    int sr[2], sc[2];
    uint32_t sdst[2];
#pragma unroll
    for (int i = 0; i < 2; i++) {
        int idx = tid + i * 256;
        sr[i] = idx >> 2;
        sc[i] = idx & 3;
        sdst[i] = sr[i] * 64 + ((sc[i] ^ ((sr[i] >> 1) & 3)) << 4);
    }
    const int lr = lane & 15, lh = lane >> 4;
    uint32_t aoff[4][2], boff[2][2];
#pragma unroll
    for (int mf = 0; mf < 4; mf++)
#pragma unroll
        for (int ks = 0; ks < 2; ks++) {
            int R = (wid & 1) * 64 + mf * 16 + lr;
            int ch = ks * 2 + lh;
            aoff[mf][ks] = R * 64 + ((ch ^ ((R >> 1) & 3)) << 4);
        }
#pragma unroll
    for (int p = 0; p < 2; p++)
#pragma unroll
        for (int ks = 0; ks < 2; ks++) {
            int R = (wid >> 1) * 32 + p * 16 + lr;
            int ch = ks * 2 + lh;
            boff[p][ks] = R * 64 + ((ch ^ ((R >> 1) & 3)) << 4);
        }

    float acc[4][4][4];
#pragma unroll
    for (int mf = 0; mf < 4; mf++)
#pragma unroll
        for (int nf = 0; nf < 4; nf++)
#pragma unroll
            for (int r = 0; r < 4; r++) acc[mf][nf][r] = 0.f;

    const int nch = K / 32;

    auto stage = [&](int c) {
        const int kc = c * 32;
        const bf16 *Ah_, *Al_;
        int lda_, kl = kc;
        if (kc < KA1) { Ah_ = A1hb; Al_ = A1lb; lda_ = lda1; }
        else          { Ah_ = A2hb; Al_ = A2lb; lda_ = lda2; kl = kc - KA1; }
        const uint32_t sb = smb + (uint32_t)(c & 3) * STG_BYTES;
#pragma unroll
        for (int i = 0; i < 2; i++) {
            const int r = sr[i], cc = sc[i];
            const uint32_t d = sdst[i];
            CP16(sb + d,         Ah_ + (size_t)(row0 + r) * lda_ + kl + cc * 8);
            CP16(sb + 8192 + d,  Al_ + (size_t)(row0 + r) * lda_ + kl + cc * 8);
            CP16(sb + 16384 + d, Bhb + (size_t)r * ldb + kc + cc * 8);
            CP16(sb + 24576 + d, Blb + (size_t)r * ldb + kc + cc * 8);
        }
        CP_COMMIT();
    };

    stage(0); stage(1); stage(2);

    for (int c = 0; c < nch; c++) {
        asm volatile("cp.async.wait_group 2;" ::: "memory");
        __syncthreads();
        const uint32_t sb = smb + (uint32_t)(c & 3) * STG_BYTES;
#pragma unroll
        for (int ks = 0; ks < 2; ks++) {
            uint32_t ah[4][4], al[4][4], bh[4][2], bl[4][2];
#pragma unroll
            for (int mf = 0; mf < 4; mf++) {
                LDSM4(ah[mf][0], ah[mf][1], ah[mf][2], ah[mf][3], sb + aoff[mf][ks]);
                LDSM4(al[mf][0], al[mf][1], al[mf][2], al[mf][3],
                      sb + 8192 + aoff[mf][ks]);
            }
#pragma unroll
            for (int p = 0; p < 2; p++) {
                uint32_t t0, t1, t2, t3;
                LDSM4(t0, t1, t2, t3, sb + 16384 + boff[p][ks]);
                bh[2 * p][0] = t0; bh[2 * p][1] = t2;
                bh[2 * p + 1][0] = t1; bh[2 * p + 1][1] = t3;
                LDSM4(t0, t1, t2, t3, sb + 24576 + boff[p][ks]);
                bl[2 * p][0] = t0; bl[2 * p][1] = t2;
                bl[2 * p + 1][0] = t1; bl[2 * p + 1][1] = t3;
            }
#pragma unroll
            for (int mf = 0; mf < 4; mf++)
#pragma unroll
                for (int nf = 0; nf < 4; nf++) {
                    mma_bf16(acc[mf][nf], ah[mf], bh[nf]);
                    mma_bf16(acc[mf][nf], ah[mf], bl[nf]);
                    mma_bf16(acc[mf][nf], al[mf], bh[nf]);
                }
        }
        if (c + 3 < nch) stage(c + 3);
        else CP_COMMIT();
    }

    const int g = lane >> 2, t2 = (lane & 3) * 2;
#pragma unroll
    for (int mf = 0; mf < 4; mf++) {
        const int gm = row0 + (wid & 1) * 64 + mf * 16 + g;
#pragma unroll
        for (int nf = 0; nf < 4; nf++) {
            const int gn = col0 + (wid >> 1) * 32 + nf * 8 + t2;
            float c0 = acc[mf][nf][0] * scale, c1 = acc[mf][nf][1] * scale;
            float c2 = acc[mf][nf][2] * scale, c3 = acc[mf][nf][3] * scale;
            if (OUT == 2) {
                float* Dfb = (float*)Dp + (long long)b * sD;
                Dfb[(size_t)gn * ldd + gm] = c0;
                Dfb[(size_t)(gn + 1) * ldd + gm] = c1;
                Dfb[(size_t)gn * ldd + gm + 8] = c2;
                Dfb[(size_t)(gn + 1) * ldd + gm + 8] = c3;
            } else {  // OUT == 4: fp16 plane row-major
                __half* Dxb = (__half*)Dp + (long long)b * sD;
                __half2 a01 = __floats2half2_rn(c0, c1);
                __half2 a23 = __floats2half2_rn(c2, c3);
                *reinterpret_cast<__half2*>(&Dxb[(size_t)gm * ldd + gn]) = a01;
                *reinterpret_cast<__half2*>(&Dxb[(size_t)(gm + 8) * ldd + gn]) = a23;
            }
        }
    }
}

// ---------------- fused attention (FA2, no-max unnormalized softmax) -------
// Logits are in log2 domain (log2e/16 folded into q). P = ex2.f16x2(S).
// Row sums accumulated per-lane; single shuffle reduction at the end.
#define FM_SMEM 196608

__global__ __launch_bounds__(256, 1) void fmha(
    const __half* __restrict__ qf, const __half* __restrict__ kf,
    const __half* __restrict__ vf,
    bf16* __restrict__ chp, bf16* __restrict__ clp)
{
    extern __shared__ char sm[];
    const uint32_t smb = smem_u32(sm);
    const uint32_t Qs = smb;
    const int tid = threadIdx.x, wid = tid >> 5, lane = tid & 31;
    const int b = blockIdx.z, row0 = blockIdx.x * 128;
    const long long sQ = (long long)NNq * CTq;
    const __half* __restrict__ qb = qf + b * sQ + (long long)row0 * CTq;
    const __half* __restrict__ kb = kf + b * sQ;
    const __half* __restrict__ vb = vf + b * sQ;

#pragma unroll
    for (int i = 0; i < 16; i++) {
        int idx = tid + i * 256;
        int row = idx >> 5, cc = idx & 31;
        uint32_t dst = Qs + (cc >> 2) * 8192 + row * 64 +
                       (uint32_t)(((cc & 3) ^ ((row >> 1) & 3)) << 4);
        CP16(dst, qb + (size_t)row * 256 + cc * 8);
    }
    CP_COMMIT();

    auto stage = [&](int c) {
        uint32_t sb = smb + 65536 + (uint32_t)(c & 3) * 32768;
        const __half* ks_ = kb + (size_t)c * 32 * 256;
        const __half* vs_ = vb + (size_t)c * 32 * 256;
#pragma unroll
        for (int i = 0; i < 4; i++) {
            int idx = tid + i * 256;
            int row = idx >> 5, cc = idx & 31;
            uint32_t off = (cc >> 2) * 2048 + row * 64 +
                           (uint32_t)(((cc & 3) ^ ((row >> 1) & 3)) << 4);
            CP16(sb + off, ks_ + (size_t)row * 256 + cc * 8);
            CP16(sb + 16384 + off, vs_ + (size_t)row * 256 + cc * 8);
        }
        CP_COMMIT();
    };
    stage(0); stage(1); stage(2);

    float o[32][4];
#pragma unroll
    for (int nt = 0; nt < 32; nt++)
#pragma unroll
        for (int j = 0; j < 4; j++) o[nt][j] = 0.f;
    float l0 = 0.f, l1 = 0.f;

    const int lr = lane & 15, lh = lane >> 4;
    const uint32_t qrow = (uint32_t)(wid * 16 + lr);
    const uint32_t qoff = qrow * 64;
    const uint32_t qswz = (qrow >> 1) & 3;
    const uint32_t krA = (uint32_t)lr * 64;
    const uint32_t krB = (uint32_t)(16 + lr) * 64;
    const uint32_t kswz = ((uint32_t)lr >> 1) & 3;

    for (int c = 0; c < 128; c++) {
        asm volatile("cp.async.wait_group 2;" ::: "memory");
        __syncthreads();
        if (c + 3 < 128) stage(c + 3);
        else CP_COMMIT();
        const uint32_t Ks = smb + 65536 + (uint32_t)(c & 3) * 32768;
        const uint32_t Vs = Ks + 16384;

        // ---- S = Q K^T (log2 domain) ----
        float s[4][4];
#pragma unroll
        for (int j = 0; j < 4; j++)
#pragma unroll
            for (int r = 0; r < 4; r++) s[j][r] = 0.f;
#pragma unroll
        for (int ks = 0; ks < 16; ks++) {
            uint32_t qa[4];
            LDSM4(qa[0], qa[1], qa[2], qa[3],
                  Qs + (ks >> 1) * 8192 + qoff +
                  (((uint32_t)((ks & 1) * 2 + lh) ^ qswz) << 4));
            const uint32_t kc = ((uint32_t)((ks & 1) * 2 + lh) ^ kswz) << 4;
            const uint32_t kp = (ks >> 1) * 2048;
            uint32_t t0, t1, t2, t3;
            LDSM4(t0, t1, t2, t3, Ks + kp + krA + kc);
            mma_f16(s[0], qa, t0, t2);
            mma_f16(s[1], qa, t1, t3);
            LDSM4(t0, t1, t2, t3, Ks + kp + krB + kc);
            mma_f16(s[2], qa, t0, t2);
            mma_f16(s[3], qa, t1, t3);
        }

        // ---- P = 2^S (fp16x2), accumulate row sums, no max/no rescale ----
        uint32_t pk[2][4];
        __half2 hs0 = __floats2half2_rn(0.f, 0.f);
        __half2 hs1 = hs0;
#pragma unroll
        for (int h = 0; h < 2; h++) {
            pk[h][0] = ex2_h2(pack_h2(s[2 * h][0], s[2 * h][1]));
            pk[h][1] = ex2_h2(pack_h2(s[2 * h][2], s[2 * h][3]));
            pk[h][2] = ex2_h2(pack_h2(s[2 * h + 1][0], s[2 * h + 1][1]));
            pk[h][3] = ex2_h2(pack_h2(s[2 * h + 1][2], s[2 * h + 1][3]));
            hs0 = __hadd2(hs0, __hadd2(*reinterpret_cast<__half2*>(&pk[h][0]),
                                       *reinterpret_cast<__half2*>(&pk[h][2])));
            hs1 = __hadd2(hs1, __hadd2(*reinterpret_cast<__half2*>(&pk[h][1]),
                                       *reinterpret_cast<__half2*>(&pk[h][3])));
        }
        float2 f0 = __half22float2(hs0);
        float2 f1 = __half22float2(hs1);
        l0 += f0.x + f0.y;
        l1 += f1.x + f1.y;

        // ---- O += P V ----
#pragma unroll
        for (int h = 0; h < 2; h++) {
            const uint32_t vr = (h == 0) ? krA : krB;
#pragma unroll
            for (int g2 = 0; g2 < 16; g2++) {
                uint32_t v0, v1, v2, v3;
                LDSM4T(v0, v1, v2, v3,
                       Vs + (g2 >> 1) * 2048 + vr +
                       (((uint32_t)((g2 & 1) * 2 + lh) ^ kswz) << 4));
                mma_f16(o[2 * g2], pk[h], v0, v1);
                mma_f16(o[2 * g2 + 1], pk[h], v2, v3);
            }
        }
    }
    asm volatile("cp.async.wait_group 0;" ::: "memory");

    // ---- final row-sum reduction (deferred) ----
    l0 += __shfl_xor_sync(0xffffffffu, l0, 1);
    l0 += __shfl_xor_sync(0xffffffffu, l0, 2);
    l1 += __shfl_xor_sync(0xffffffffu, l1, 1);
    l1 += __shfl_xor_sync(0xffffffffu, l1, 2);

    const int g = lane >> 2, t2 = (lane & 3) * 2;
    const float i0 = 1.0f / l0, i1 = 1.0f / l1;
    bf16* __restrict__ chb = chp + b * sQ;
    bf16* __restrict__ clb = clp + b * sQ;
    const int gm0 = row0 + wid * 16 + g;
#pragma unroll
    for (int nt = 0; nt < 32; nt++) {
        const int gn = nt * 8 + t2;
        float c0 = o[nt][0] * i0, c1 = o[nt][1] * i0;
        float c2 = o[nt][2] * i1, c3 = o[nt][3] * i1;
        bf16 h0 = __float2bfloat16(c0), h1 = __float2bfloat16(c1);
        bf16 h2 = __float2bfloat16(c2), h3 = __float2bfloat16(c3);
        bf162 hv0; hv0.x = h0; hv0.y = h1;
        bf162 hv1; hv1.x = h2; hv1.y = h3;
        bf162 lv0; lv0.x = __float2bfloat16(c0 - __bfloat162float(h0));
        lv0.y = __float2bfloat16(c1 - __bfloat162float(h1));
        bf162 lv1; lv1.x = __float2bfloat16(c2 - __bfloat162float(h2));
        lv1.y = __float2bfloat16(c3 - __bfloat162float(h3));
        *reinterpret_cast<bf162*>(&chb[(size_t)gm0 * CTq + gn]) = hv0;
        *reinterpret_cast<bf162*>(&chb[(size_t)(gm0 + 8) * CTq + gn]) = hv1;
        *reinterpret_cast<bf162*>(&clb[(size_t)gm0 * CTq + gn]) = lv0;
        *reinterpret_cast<bf162*>(&clb[(size_t)(gm0 + 8) * CTq + gn]) = lv1;
    }
}

// ---------------- x transpose + split ----------------
__global__ __launch_bounds__(256) void transpose_split(
    const float* __restrict__ x, bf16* __restrict__ xth, bf16* __restrict__ xtl)
{
    __shared__ float t[32][33];
    const int b = blockIdx.z;
    const int n0 = blockIdx.x * 32, c0 = blockIdx.y * 32;
    const int tx = threadIdx.x & 31, ty = threadIdx.x >> 5;
    const float* xb = x + (size_t)b * CCq * NNq;
    bf16* xh = xth + (size_t)b * NNq * CCq;
    bf16* xl = xtl + (size_t)b * NNq * CCq;
#pragma unroll
    for (int p = 0; p < 4; p++)
        t[ty + p * 8][tx] = xb[(size_t)(c0 + ty + p * 8) * NNq + n0 + tx];
    __syncthreads();
#pragma unroll
    for (int p = 0; p < 4; p++) {
        float v = t[tx][ty + p * 8];
        bf16 h = __float2bfloat16(v);
        xh[(size_t)(n0 + ty + p * 8) * CCq + c0 + tx] = h;
        xl[(size_t)(n0 + ty + p * 8) * CCq + c0 + tx] =
            __float2bfloat16(v - __bfloat162float(h));
    }
}

__global__ __launch_bounds__(256) void wsplit(const float* __restrict__ w,
                                              bf16* __restrict__ h,
                                              bf16* __restrict__ l, int n)
{
    int i = blockIdx.x * 256 + threadIdx.x;
    if (i < n) {
        float v = w[i];
        bf16 hh = __float2bfloat16(v);
        h[i] = hh;
        l[i] = __float2bfloat16(v - __bfloat162float(hh));
    }
}

// ---------------- launch ----------------
extern "C" void kernel_launch(void* const* d_in, const int* in_sizes, int n_in,
                              void* d_out, int out_size)
{
    const float* x  = (const float*)d_in[0];
    const float* Wq = (const float*)d_in[1];
    const float* Wk = (const float*)d_in[2];
    const float* Wv = (const float*)d_in[3];
    const float* Wo = (const float*)d_in[4];
    float* out = (float*)d_out;

    void *xth, *xtl, *qf, *kf, *vf, *ch, *cl;
    void *wqh, *wql, *wkh, *wkl, *wvh, *wvl, *woh, *wol;
    cudaGetSymbolAddress(&xth, g_xth); cudaGetSymbolAddress(&xtl, g_xtl);
    cudaGetSymbolAddress(&qf, g_qf);   cudaGetSymbolAddress(&kf, g_kf);
    cudaGetSymbolAddress(&vf, g_vf);
    cudaGetSymbolAddress(&ch, g_ch);   cudaGetSymbolAddress(&cl, g_cl);
    cudaGetSymbolAddress(&wqh, g_wqh); cudaGetSymbolAddress(&wql, g_wql);
    cudaGetSymbolAddress(&wkh, g_wkh); cudaGetSymbolAddress(&wkl, g_wkl);
    cudaGetSymbolAddress(&wvh, g_wvh); cudaGetSymbolAddress(&wvl, g_wvl);
    cudaGetSymbolAddress(&woh, g_woh); cudaGetSymbolAddress(&wol, g_wol);

    cudaFuncSetAttribute(gemm_pl<2>, cudaFuncAttributeMaxDynamicSharedMemorySize, GSMEM);
    cudaFuncSetAttribute(gemm_pl<4>, cudaFuncAttributeMaxDynamicSharedMemorySize, GSMEM);
    cudaFuncSetAttribute(fmha, cudaFuncAttributeMaxDynamicSharedMemorySize, FM_SMEM);

    const long long sX = (long long)NNq * CCq;
    const long long sQ = (long long)NNq * CTq;
    dim3 blk(256);

    transpose_split<<<dim3(NNq / 32, CCq / 32, BBq), blk>>>(
        x, (bf16*)xth, (bf16*)xtl);
    wsplit<<<dim3(CTq * CCq / 256), blk>>>(Wq, (bf16*)wqh, (bf16*)wql, CTq * CCq);
    wsplit<<<dim3(CTq * CCq / 256), blk>>>(Wk, (bf16*)wkh, (bf16*)wkl, CTq * CCq);
    wsplit<<<dim3(CTq * CCq / 256), blk>>>(Wv, (bf16*)wvh, (bf16*)wvl, CTq * CCq);
    wsplit<<<dim3(CCq * 2 * CTq / 256), blk>>>(Wo, (bf16*)woh, (bf16*)wol,
                                               CCq * 2 * CTq);

    // q pre-scaled by log2e/16 so fmha logits are in log2 domain
    gemm_pl<4><<<dim3(32, 2, BBq), blk, GSMEM>>>(
        (bf16*)xth, (bf16*)xtl, CCq, sX, nullptr, nullptr, 0, 0, CCq,
        (bf16*)wqh, (bf16*)wql, CCq, 0, qf, CTq, sQ, CCq,
        0.0625f * 1.44269504089f);
    gemm_pl<4><<<dim3(32, 2, BBq), blk, GSMEM>>>(
        (bf16*)xth, (bf16*)xtl, CCq, sX, nullptr, nullptr, 0, 0, CCq,
        (bf16*)wkh, (bf16*)wkl, CCq, 0, kf, CTq, sQ, CCq, 1.0f);
    gemm_pl<4><<<dim3(32, 2, BBq), blk, GSMEM>>>(
        (bf16*)xth, (bf16*)xtl, CCq, sX, nullptr, nullptr, 0, 0, CCq,
        (bf16*)wvh, (bf16*)wvl, CCq, 0, vf, CTq, sQ, CCq, 1.0f);

    fmha<<<dim3(32, 1, BBq), blk, FM_SMEM>>>(
        (const __half*)qf, (const __half*)kf, (const __half*)vf,
        (bf16*)ch, (bf16*)cl);

    gemm_pl<2><<<dim3(32, 2, BBq), blk, GSMEM>>>(
        (bf16*)ch, (bf16*)cl, CTq, sQ, (bf16*)xth, (bf16*)xtl, CCq, sX, CTq,
        (bf16*)woh, (bf16*)wol, 2 * CTq, 0,
        out, NNq, (long long)CCq * NNq, 2 * CTq, 1.0f);
}

// round 10
// speedup vs baseline: 7.5276x; 1.3196x over previous
#include <cuda_runtime.h>
#include <cuda_bf16.h>
#include <cuda_fp16.h>
#include <cstdint>

#define BBq 4
#define CCq 256
#define NNq 4096
#define CTq 256

typedef __nv_bfloat16 bf16;
typedef __nv_bfloat162 bf162;

// ---------------- persistent planes (device globals) ----------------
__device__ __align__(256) bf16   g_xth[(size_t)BBq * NNq * CCq];
__device__ __align__(256) bf16   g_xtl[(size_t)BBq * NNq * CCq];
__device__ __align__(256) __half g_xtf[(size_t)BBq * NNq * CCq];
__device__ __align__(256) __half g_qf [(size_t)BBq * NNq * CTq];
__device__ __align__(256) __half g_kf [(size_t)BBq * NNq * CTq];
__device__ __align__(256) __half g_vf [(size_t)BBq * NNq * CTq];
__device__ __align__(256) bf16   g_ch [(size_t)BBq * NNq * CTq];
__device__ __align__(256) bf16   g_cl [(size_t)BBq * NNq * CTq];
__device__ __align__(256) __half g_wqf[CTq * CCq];
__device__ __align__(256) __half g_wkf[CTq * CCq];
__device__ __align__(256) __half g_wvf[CTq * CCq];
__device__ __align__(256) bf16   g_woh[CCq * 2 * CTq];
__device__ __align__(256) bf16   g_wol[CCq * 2 * CTq];

// ---------------- helpers ----------------
__device__ __forceinline__ uint32_t smem_u32(const void* p) {
    uint32_t a;
    asm("{ .reg .u64 t; cvta.to.shared.u64 t, %1; cvt.u32.u64 %0, t; }"
        : "=r"(a) : "l"(p));
    return a;
}
#define CP16(dst, src) \
    asm volatile("cp.async.cg.shared.global [%0], [%1], 16;" \
                 :: "r"(dst), "l"(src))
#define CP_COMMIT() asm volatile("cp.async.commit_group;" ::: "memory")

#define LDSM4(r0, r1, r2, r3, addr) \
    asm volatile("ldmatrix.sync.aligned.m8n8.x4.shared.b16 {%0,%1,%2,%3}, [%4];" \
                 : "=r"(r0), "=r"(r1), "=r"(r2), "=r"(r3) : "r"(addr))
#define LDSM4T(r0, r1, r2, r3, addr) \
    asm volatile("ldmatrix.sync.aligned.m8n8.x4.trans.shared.b16 {%0,%1,%2,%3}, [%4];" \
                 : "=r"(r0), "=r"(r1), "=r"(r2), "=r"(r3) : "r"(addr))

__device__ __forceinline__ void mma_bf16(float* d, const uint32_t* a,
                                         const uint32_t* b) {
    asm volatile(
        "mma.sync.aligned.m16n8k16.row.col.f32.bf16.bf16.f32 "
        "{%0,%1,%2,%3}, {%4,%5,%6,%7}, {%8,%9}, {%0,%1,%2,%3};"
        : "+f"(d[0]), "+f"(d[1]), "+f"(d[2]), "+f"(d[3])
        : "r"(a[0]), "r"(a[1]), "r"(a[2]), "r"(a[3]), "r"(b[0]), "r"(b[1]));
}
__device__ __forceinline__ void mma_f16(float* d, const uint32_t* a,
                                        uint32_t b0, uint32_t b1) {
    asm volatile(
        "mma.sync.aligned.m16n8k16.row.col.f32.f16.f16.f32 "
        "{%0,%1,%2,%3}, {%4,%5,%6,%7}, {%8,%9}, {%0,%1,%2,%3};"
        : "+f"(d[0]), "+f"(d[1]), "+f"(d[2]), "+f"(d[3])
        : "r"(a[0]), "r"(a[1]), "r"(a[2]), "r"(a[3]), "r"(b0), "r"(b1));
}
__device__ __forceinline__ uint32_t pack_h2(float a, float b) {
    __half2 h = __floats2half2_rn(a, b);
    return *reinterpret_cast<uint32_t*>(&h);
}
__device__ __forceinline__ uint32_t ex2_h2(uint32_t x) {
    uint32_t r;
    asm("ex2.approx.f16x2 %0, %1;" : "=r"(r) : "r"(x));
    return r;
}

// ---------------- fused qkv: single-term fp16 GEMM ----------------
// grid (32, 2, BBq*3): z selects (b, which of q/k/v).
// D[128x128] = xtf[128,256] * W[128,256]^T, fp16 in/out, fp32 accum.
#define QSTG 16384
#define QSMEM (4 * QSTG)

__global__ __launch_bounds__(256, 1) void qkv_f16(
    const __half* __restrict__ xtf,
    const __half* __restrict__ Wq, const __half* __restrict__ Wk,
    const __half* __restrict__ Wv,
    __half* __restrict__ qf, __half* __restrict__ kf, __half* __restrict__ vf)
{
    extern __shared__ char sm[];
    const uint32_t smb = smem_u32(sm);
    const int tid = threadIdx.x;
    const int wid = tid >> 5, lane = tid & 31;
    const int w = blockIdx.z % 3, b = blockIdx.z / 3;
    const int row0 = blockIdx.x * 128;
    const int col0 = blockIdx.y * 128;

    const __half* __restrict__ W = (w == 0) ? Wq : (w == 1) ? Wk : Wv;
    __half* __restrict__ D = (w == 0) ? qf : (w == 1) ? kf : vf;
    const float scale = (w == 0) ? 0.0625f * 1.44269504089f : 1.0f;

    const __half* __restrict__ Ab =
        xtf + (long long)b * NNq * CCq + (long long)row0 * CCq;
    const __half* __restrict__ Bb = W + (long long)col0 * CCq;

    int sr[2], sc[2];
    uint32_t sdst[2];
#pragma unroll
    for (int i = 0; i < 2; i++) {
        int idx = tid + i * 256;
        sr[i] = idx >> 2;
        sc[i] = idx & 3;
        sdst[i] = sr[i] * 64 + ((sc[i] ^ ((sr[i] >> 1) & 3)) << 4);
    }
    const int lr = lane & 15, lh = lane >> 4;
    uint32_t aoff[4][2], boff[2][2];
#pragma unroll
    for (int mf = 0; mf < 4; mf++)
#pragma unroll
        for (int ks = 0; ks < 2; ks++) {
            int R = (wid & 1) * 64 + mf * 16 + lr;
            int ch = ks * 2 + lh;
            aoff[mf][ks] = R * 64 + ((ch ^ ((R >> 1) & 3)) << 4);
        }
#pragma unroll
    for (int p = 0; p < 2; p++)
#pragma unroll
        for (int ks = 0; ks < 2; ks++) {
            int R = (wid >> 1) * 32 + p * 16 + lr;
            int ch = ks * 2 + lh;
            boff[p][ks] = R * 64 + ((ch ^ ((R >> 1) & 3)) << 4);
        }

    float acc[4][4][4];
#pragma unroll
    for (int mf = 0; mf < 4; mf++)
#pragma unroll
        for (int nf = 0; nf < 4; nf++)
#pragma unroll
            for (int r = 0; r < 4; r++) acc[mf][nf][r] = 0.f;

    auto stage = [&](int c) {
        const int kc = c * 32;
        const uint32_t sb = smb + (uint32_t)(c & 3) * QSTG;
#pragma unroll
        for (int i = 0; i < 2; i++) {
            CP16(sb + sdst[i],        Ab + (size_t)sr[i] * CCq + kc + sc[i] * 8);
            CP16(sb + 8192 + sdst[i], Bb + (size_t)sr[i] * CCq + kc + sc[i] * 8);
        }
        CP_COMMIT();
    };
    stage(0); stage(1); stage(2);

    for (int c = 0; c < 8; c++) {
        asm volatile("cp.async.wait_group 2;" ::: "memory");
        __syncthreads();
        const uint32_t sb = smb + (uint32_t)(c & 3) * QSTG;
#pragma unroll
        for (int ks = 0; ks < 2; ks++) {
            uint32_t ah[4][4], bh[4][2];
#pragma unroll
            for (int mf = 0; mf < 4; mf++)
                LDSM4(ah[mf][0], ah[mf][1], ah[mf][2], ah[mf][3], sb + aoff[mf][ks]);
#pragma unroll
            for (int p = 0; p < 2; p++) {
                uint32_t t0, t1, t2, t3;
                LDSM4(t0, t1, t2, t3, sb + 8192 + boff[p][ks]);
                bh[2 * p][0] = t0; bh[2 * p][1] = t2;
                bh[2 * p + 1][0] = t1; bh[2 * p + 1][1] = t3;
            }
#pragma unroll
            for (int mf = 0; mf < 4; mf++)
#pragma unroll
                for (int nf = 0; nf < 4; nf++)
                    mma_f16(acc[mf][nf], ah[mf], bh[nf][0], bh[nf][1]);
        }
        if (c + 3 < 8) stage(c + 3);
        else CP_COMMIT();
    }

    const int g = lane >> 2, t2 = (lane & 3) * 2;
    __half* __restrict__ Db = D + (long long)b * NNq * CTq;
#pragma unroll
    for (int mf = 0; mf < 4; mf++) {
        const int gm = row0 + (wid & 1) * 64 + mf * 16 + g;
#pragma unroll
        for (int nf = 0; nf < 4; nf++) {
            const int gn = col0 + (wid >> 1) * 32 + nf * 8 + t2;
            __half2 a01 = __floats2half2_rn(acc[mf][nf][0] * scale,
                                            acc[mf][nf][1] * scale);
            __half2 a23 = __floats2half2_rn(acc[mf][nf][2] * scale,
                                            acc[mf][nf][3] * scale);
            *reinterpret_cast<__half2*>(&Db[(size_t)gm * CTq + gn]) = a01;
            *reinterpret_cast<__half2*>(&Db[(size_t)(gm + 8) * CTq + gn]) = a23;
        }
    }
}

// ---------------- bf16-plane 3-term GEMM (out projection only) ----------------
#define STG_BYTES 32768
#define GSMEM (4 * STG_BYTES)

__global__ __launch_bounds__(256, 1) void gemm_out(
    const bf16* __restrict__ A1h, const bf16* __restrict__ A1l, int lda1, long long sA1,
    const bf16* __restrict__ A2h, const bf16* __restrict__ A2l, int lda2, long long sA2,
    int KA1,
    const bf16* __restrict__ Bh, const bf16* __restrict__ Bl, int ldb,
    float* __restrict__ Df, int ldd, long long sD, int K)
{
    extern __shared__ char sm[];
    const uint32_t smb = smem_u32(sm);
    const int tid = threadIdx.x;
    const int wid = tid >> 5, lane = tid & 31;
    const int row0 = blockIdx.x * 128;
    const int col0 = blockIdx.y * 128;
    const int b = blockIdx.z;

    const bf16* __restrict__ A1hb = A1h + (long long)b * sA1;
    const bf16* __restrict__ A1lb = A1l + (long long)b * sA1;
    const bf16* __restrict__ A2hb = A2h + (long long)b * sA2;
    const bf16* __restrict__ A2lb = A2l + (long long)b * sA2;
    const bf16* __restrict__ Bhb = Bh + (size_t)col0 * ldb;
    const bf16* __restrict__ Blb = Bl + (size_t)col0 * ldb;

    int sr[2], sc[2];
    uint32_t sdst[2];
#pragma unroll
    for (int i = 0; i < 2; i++) {
        int idx = tid + i * 256;
        sr[i] = idx >> 2;
        sc[i] = idx & 3;
        sdst[i] = sr[i] * 64 + ((sc[i] ^ ((sr[i] >> 1) & 3)) << 4);
    }
    const int lr = lane & 15, lh = lane >> 4;
    uint32_t aoff[4][2], boff[2][2];
#pragma unroll
    for (int mf = 0; mf < 4; mf++)
#pragma unroll
        for (int ks = 0; ks < 2; ks++) {
            int R = (wid & 1) * 64 + mf * 16 + lr;
            int ch = ks * 2 + lh;
            aoff[mf][ks] = R * 64 + ((ch ^ ((R >> 1) & 3)) << 4);
        }
#pragma unroll
    for (int p = 0; p < 2; p++)
#pragma unroll
        for (int ks = 0; ks < 2; ks++) {
            int R = (wid >> 1) * 32 + p * 16 + lr;
            int ch = ks * 2 + lh;
            boff[p][ks] = R * 64 + ((ch ^ ((R >> 1) & 3)) << 4);
        }

    float acc[4][4][4];
#pragma unroll
    for (int mf = 0; mf < 4; mf++)
#pragma unroll
        for (int nf = 0; nf < 4; nf++)
#pragma unroll
            for (int r = 0; r < 4; r++) acc[mf][nf][r] = 0.f;

    const int nch = K / 32;

    auto stage = [&](int c) {
        const int kc = c * 32;
        const bf16 *Ah_, *Al_;
        int lda_, kl = kc;
        if (kc < KA1) { Ah_ = A1hb; Al_ = A1lb; lda_ = lda1; }
        else          { Ah_ = A2hb; Al_ = A2lb; lda_ = lda2; kl = kc - KA1; }
        const uint32_t sb = smb + (uint32_t)(c & 3) * STG_BYTES;
#pragma unroll
        for (int i = 0; i < 2; i++) {
            const int r = sr[i], cc = sc[i];
            const uint32_t d = sdst[i];
            CP16(sb + d,         Ah_ + (size_t)(row0 + r) * lda_ + kl + cc * 8);
            CP16(sb + 8192 + d,  Al_ + (size_t)(row0 + r) * lda_ + kl + cc * 8);
            CP16(sb + 16384 + d, Bhb + (size_t)r * ldb + kc + cc * 8);
            CP16(sb + 24576 + d, Blb + (size_t)r * ldb + kc + cc * 8);
        }
        CP_COMMIT();
    };

    stage(0); stage(1); stage(2);

    for (int c = 0; c < nch; c++) {
        asm volatile("cp.async.wait_group 2;" ::: "memory");
        __syncthreads();
        const uint32_t sb = smb + (uint32_t)(c & 3) * STG_BYTES;
#pragma unroll
        for (int ks = 0; ks < 2; ks++) {
            uint32_t ah[4][4], al[4][4], bh[4][2], bl[4][2];
#pragma unroll
            for (int mf = 0; mf < 4; mf++) {
                LDSM4(ah[mf][0], ah[mf][1], ah[mf][2], ah[mf][3], sb + aoff[mf][ks]);
                LDSM4(al[mf][0], al[mf][1], al[mf][2], al[mf][3],
                      sb + 8192 + aoff[mf][ks]);
            }
#pragma unroll
            for (int p = 0; p < 2; p++) {
                uint32_t t0, t1, t2, t3;
                LDSM4(t0, t1, t2, t3, sb + 16384 + boff[p][ks]);
                bh[2 * p][0] = t0; bh[2 * p][1] = t2;
                bh[2 * p + 1][0] = t1; bh[2 * p + 1][1] = t3;
                LDSM4(t0, t1, t2, t3, sb + 24576 + boff[p][ks]);
                bl[2 * p][0] = t0; bl[2 * p][1] = t2;
                bl[2 * p + 1][0] = t1; bl[2 * p + 1][1] = t3;
            }
#pragma unroll
            for (int mf = 0; mf < 4; mf++)
#pragma unroll
                for (int nf = 0; nf < 4; nf++) {
                    mma_bf16(acc[mf][nf], ah[mf], bh[nf]);
                    mma_bf16(acc[mf][nf], ah[mf], bl[nf]);
                    mma_bf16(acc[mf][nf], al[mf], bh[nf]);
                }
        }
        if (c + 3 < nch) stage(c + 3);
        else CP_COMMIT();
    }

    const int g = lane >> 2, t2 = (lane & 3) * 2;
    float* __restrict__ Dfb = Df + (long long)b * sD;
#pragma unroll
    for (int mf = 0; mf < 4; mf++) {
        const int gm = row0 + (wid & 1) * 64 + mf * 16 + g;
#pragma unroll
        for (int nf = 0; nf < 4; nf++) {
            const int gn = col0 + (wid >> 1) * 32 + nf * 8 + t2;
            Dfb[(size_t)gn * ldd + gm] = acc[mf][nf][0];
            Dfb[(size_t)(gn + 1) * ldd + gm] = acc[mf][nf][1];
            Dfb[(size_t)gn * ldd + gm + 8] = acc[mf][nf][2];
            Dfb[(size_t)(gn + 1) * ldd + gm + 8] = acc[mf][nf][3];
        }
    }
}

// ---------------- fused attention (no-max softmax, Q in registers) ---------
#define FM_SMEM 196608

__global__ __launch_bounds__(256, 1) void fmha(
    const __half* __restrict__ qf, const __half* __restrict__ kf,
    const __half* __restrict__ vf,
    bf16* __restrict__ chp, bf16* __restrict__ clp)
{
    extern __shared__ char sm[];
    const uint32_t smb = smem_u32(sm);
    const uint32_t Qs = smb;
    const int tid = threadIdx.x, wid = tid >> 5, lane = tid & 31;
    const int b = blockIdx.z, row0 = blockIdx.x * 128;
    const long long sQ = (long long)NNq * CTq;
    const __half* __restrict__ qb = qf + b * sQ + (long long)row0 * CTq;
    const __half* __restrict__ kb = kf + b * sQ;
    const __half* __restrict__ vb = vf + b * sQ;

#pragma unroll
    for (int i = 0; i < 16; i++) {
        int idx = tid + i * 256;
        int row = idx >> 5, cc = idx & 31;
        uint32_t dst = Qs + (cc >> 2) * 8192 + row * 64 +
                       (uint32_t)(((cc & 3) ^ ((row >> 1) & 3)) << 4);
        CP16(dst, qb + (size_t)row * 256 + cc * 8);
    }
    CP_COMMIT();

    auto stage = [&](int c) {
        uint32_t sb = smb + 65536 + (uint32_t)(c & 3) * 32768;
        const __half* ks_ = kb + (size_t)c * 32 * 256;
        const __half* vs_ = vb + (size_t)c * 32 * 256;
#pragma unroll
        for (int i = 0; i < 4; i++) {
            int idx = tid + i * 256;
            int row = idx >> 5, cc = idx & 31;
            uint32_t off = (cc >> 2) * 2048 + row * 64 +
                           (uint32_t)(((cc & 3) ^ ((row >> 1) & 3)) << 4);
            CP16(sb + off, ks_ + (size_t)row * 256 + cc * 8);
            CP16(sb + 16384 + off, vs_ + (size_t)row * 256 + cc * 8);
        }
        CP_COMMIT();
    };
    stage(0); stage(1); stage(2);

    const int lr = lane & 15, lh = lane >> 4;
    const uint32_t qrow = (uint32_t)(wid * 16 + lr);
    const uint32_t qoff = qrow * 64;
    const uint32_t qswz = (qrow >> 1) & 3;
    const uint32_t krA = (uint32_t)lr * 64;
    const uint32_t krB = (uint32_t)(16 + lr) * 64;
    const uint32_t kswz = ((uint32_t)lr >> 1) & 3;

    // ---- hoist Q fragments into registers (chunk-invariant) ----
    asm volatile("cp.async.wait_group 3;" ::: "memory");
    __syncthreads();
    uint32_t qreg[16][4];
#pragma unroll
    for (int ks = 0; ks < 16; ks++)
        LDSM4(qreg[ks][0], qreg[ks][1], qreg[ks][2], qreg[ks][3],
              Qs + (ks >> 1) * 8192 + qoff +
              (((uint32_t)((ks & 1) * 2 + lh) ^ qswz) << 4));

    float o[32][4];
#pragma unroll
    for (int nt = 0; nt < 32; nt++)
#pragma unroll
        for (int j = 0; j < 4; j++) o[nt][j] = 0.f;
    float l0 = 0.f, l1 = 0.f;

    for (int c = 0; c < 128; c++) {
        asm volatile("cp.async.wait_group 2;" ::: "memory");
        __syncthreads();
        if (c + 3 < 128) stage(c + 3);
        else CP_COMMIT();
        const uint32_t Ks = smb + 65536 + (uint32_t)(c & 3) * 32768;
        const uint32_t Vs = Ks + 16384;

        float s[4][4];
#pragma unroll
        for (int j = 0; j < 4; j++)
#pragma unroll
            for (int r = 0; r < 4; r++) s[j][r] = 0.f;
#pragma unroll
        for (int ks = 0; ks < 16; ks++) {
            const uint32_t kc = ((uint32_t)((ks & 1) * 2 + lh) ^ kswz) << 4;
            const uint32_t kp = (ks >> 1) * 2048;
            uint32_t t0, t1, t2, t3;
            LDSM4(t0, t1, t2, t3, Ks + kp + krA + kc);
            mma_f16(s[0], qreg[ks], t0, t2);
            mma_f16(s[1], qreg[ks], t1, t3);
            LDSM4(t0, t1, t2, t3, Ks + kp + krB + kc);
            mma_f16(s[2], qreg[ks], t0, t2);
            mma_f16(s[3], qreg[ks], t1, t3);
        }

        uint32_t pk[2][4];
        __half2 hs0 = __floats2half2_rn(0.f, 0.f);
        __half2 hs1 = hs0;
#pragma unroll
        for (int h = 0; h < 2; h++) {
            pk[h][0] = ex2_h2(pack_h2(s[2 * h][0], s[2 * h][1]));
            pk[h][1] = ex2_h2(pack_h2(s[2 * h][2], s[2 * h][3]));
            pk[h][2] = ex2_h2(pack_h2(s[2 * h + 1][0], s[2 * h + 1][1]));
            pk[h][3] = ex2_h2(pack_h2(s[2 * h + 1][2], s[2 * h + 1][3]));
            hs0 = __hadd2(hs0, __hadd2(*reinterpret_cast<__half2*>(&pk[h][0]),
                                       *reinterpret_cast<__half2*>(&pk[h][2])));
            hs1 = __hadd2(hs1, __hadd2(*reinterpret_cast<__half2*>(&pk[h][1]),
                                       *reinterpret_cast<__half2*>(&pk[h][3])));
        }
        float2 f0 = __half22float2(hs0);
        float2 f1 = __half22float2(hs1);
        l0 += f0.x + f0.y;
        l1 += f1.x + f1.y;

#pragma unroll
        for (int h = 0; h < 2; h++) {
            const uint32_t vr = (h == 0) ? krA : krB;
#pragma unroll
            for (int g2 = 0; g2 < 16; g2++) {
                uint32_t v0, v1, v2, v3;
                LDSM4T(v0, v1, v2, v3,
                       Vs + (g2 >> 1) * 2048 + vr +
                       (((uint32_t)((g2 & 1) * 2 + lh) ^ kswz) << 4));
                mma_f16(o[2 * g2], pk[h], v0, v1);
                mma_f16(o[2 * g2 + 1], pk[h], v2, v3);
            }
        }
    }
    asm volatile("cp.async.wait_group 0;" ::: "memory");

    l0 += __shfl_xor_sync(0xffffffffu, l0, 1);
    l0 += __shfl_xor_sync(0xffffffffu, l0, 2);
    l1 += __shfl_xor_sync(0xffffffffu, l1, 1);
    l1 += __shfl_xor_sync(0xffffffffu, l1, 2);

    const int g = lane >> 2, t2 = (lane & 3) * 2;
    const float i0 = 1.0f / l0, i1 = 1.0f / l1;
    bf16* __restrict__ chb = chp + b * sQ;
    bf16* __restrict__ clb = clp + b * sQ;
    const int gm0 = row0 + wid * 16 + g;
#pragma unroll
    for (int nt = 0; nt < 32; nt++) {
        const int gn = nt * 8 + t2;
        float c0 = o[nt][0] * i0, c1 = o[nt][1] * i0;
        float c2 = o[nt][2] * i1, c3 = o[nt][3] * i1;
        bf16 h0 = __float2bfloat16(c0), h1 = __float2bfloat16(c1);
        bf16 h2 = __float2bfloat16(c2), h3 = __float2bfloat16(c3);
        bf162 hv0; hv0.x = h0; hv0.y = h1;
        bf162 hv1; hv1.x = h2; hv1.y = h3;
        bf162 lv0; lv0.x = __float2bfloat16(c0 - __bfloat162float(h0));
        lv0.y = __float2bfloat16(c1 - __bfloat162float(h1));
        bf162 lv1; lv1.x = __float2bfloat16(c2 - __bfloat162float(h2));
        lv1.y = __float2bfloat16(c3 - __bfloat162float(h3));
        *reinterpret_cast<bf162*>(&chb[(size_t)gm0 * CTq + gn]) = hv0;
        *reinterpret_cast<bf162*>(&chb[(size_t)(gm0 + 8) * CTq + gn]) = hv1;
        *reinterpret_cast<bf162*>(&clb[(size_t)gm0 * CTq + gn]) = lv0;
        *reinterpret_cast<bf162*>(&clb[(size_t)(gm0 + 8) * CTq + gn]) = lv1;
    }
}

// ---------------- x transpose + split (bf16 hi/lo + fp16) ----------------
__global__ __launch_bounds__(256) void transpose_split(
    const float* __restrict__ x, bf16* __restrict__ xth,
    bf16* __restrict__ xtl, __half* __restrict__ xtf)
{
    __shared__ float t[32][33];
    const int b = blockIdx.z;
    const int n0 = blockIdx.x * 32, c0 = blockIdx.y * 32;
    const int tx = threadIdx.x & 31, ty = threadIdx.x >> 5;
    const float* xb = x + (size_t)b * CCq * NNq;
    bf16* xh = xth + (size_t)b * NNq * CCq;
    bf16* xl = xtl + (size_t)b * NNq * CCq;
    __half* xf = xtf + (size_t)b * NNq * CCq;
#pragma unroll
    for (int p = 0; p < 4; p++)
        t[ty + p * 8][tx] = xb[(size_t)(c0 + ty + p * 8) * NNq + n0 + tx];
    __syncthreads();
#pragma unroll
    for (int p = 0; p < 4; p++) {
        float v = t[tx][ty + p * 8];
        bf16 h = __float2bfloat16(v);
        size_t idx = (size_t)(n0 + ty + p * 8) * CCq + c0 + tx;
        xh[idx] = h;
        xl[idx] = __float2bfloat16(v - __bfloat162float(h));
        xf[idx] = __float2half_rn(v);
    }
}

// qkv weights -> fp16 single plane (all three in one launch)
__global__ __launch_bounds__(256) void wconv3(
    const float* __restrict__ wq, const float* __restrict__ wk,
    const float* __restrict__ wv,
    __half* __restrict__ fq, __half* __restrict__ fk, __half* __restrict__ fv)
{
    int i = blockIdx.x * 256 + threadIdx.x;
    if (i < CTq * CCq) {
        fq[i] = __float2half_rn(wq[i]);
        fk[i] = __float2half_rn(wk[i]);
        fv[i] = __float2half_rn(wv[i]);
    }
}

__global__ __launch_bounds__(256) void wsplit(const float* __restrict__ w,
                                              bf16* __restrict__ h,
                                              bf16* __restrict__ l, int n)
{
    int i = blockIdx.x * 256 + threadIdx.x;
    if (i < n) {
        float v = w[i];
        bf16 hh = __float2bfloat16(v);
        h[i] = hh;
        l[i] = __float2bfloat16(v - __bfloat162float(hh));
    }
}

// ---------------- launch ----------------
extern "C" void kernel_launch(void* const* d_in, const int* in_sizes, int n_in,
                              void* d_out, int out_size)
{
    const float* x  = (const float*)d_in[0];
    const float* Wq = (const float*)d_in[1];
    const float* Wk = (const float*)d_in[2];
    const float* Wv = (const float*)d_in[3];
    const float* Wo = (const float*)d_in[4];
    float* out = (float*)d_out;

    void *xth, *xtl, *xtf, *qf, *kf, *vf, *ch, *cl;
    void *wqf, *wkf, *wvf, *woh, *wol;
    cudaGetSymbolAddress(&xth, g_xth); cudaGetSymbolAddress(&xtl, g_xtl);
    cudaGetSymbolAddress(&xtf, g_xtf);
    cudaGetSymbolAddress(&qf, g_qf);   cudaGetSymbolAddress(&kf, g_kf);
    cudaGetSymbolAddress(&vf, g_vf);
    cudaGetSymbolAddress(&ch, g_ch);   cudaGetSymbolAddress(&cl, g_cl);
    cudaGetSymbolAddress(&wqf, g_wqf); cudaGetSymbolAddress(&wkf, g_wkf);
    cudaGetSymbolAddress(&wvf, g_wvf);
    cudaGetSymbolAddress(&woh, g_woh); cudaGetSymbolAddress(&wol, g_wol);

    cudaFuncSetAttribute(qkv_f16, cudaFuncAttributeMaxDynamicSharedMemorySize, QSMEM);
    cudaFuncSetAttribute(gemm_out, cudaFuncAttributeMaxDynamicSharedMemorySize, GSMEM);
    cudaFuncSetAttribute(fmha, cudaFuncAttributeMaxDynamicSharedMemorySize, FM_SMEM);

    const long long sX = (long long)NNq * CCq;
    const long long sQ = (long long)NNq * CTq;
    dim3 blk(256);

    transpose_split<<<dim3(NNq / 32, CCq / 32, BBq), blk>>>(
        x, (bf16*)xth, (bf16*)xtl, (__half*)xtf);
    wconv3<<<dim3(CTq * CCq / 256), blk>>>(
        Wq, Wk, Wv, (__half*)wqf, (__half*)wkf, (__half*)wvf);
    wsplit<<<dim3(CCq * 2 * CTq / 256), blk>>>(Wo, (bf16*)woh, (bf16*)wol,
                                               CCq * 2 * CTq);

    // fused q/k/v projection (q pre-scaled by log2e/16)
    qkv_f16<<<dim3(32, 2, BBq * 3), blk, QSMEM>>>(
        (const __half*)xtf, (const __half*)wqf, (const __half*)wkf,
        (const __half*)wvf, (__half*)qf, (__half*)kf, (__half*)vf);

    fmha<<<dim3(32, 1, BBq), blk, FM_SMEM>>>(
        (const __half*)qf, (const __half*)kf, (const __half*)vf,
        (bf16*)ch, (bf16*)cl);

    gemm_out<<<dim3(32, 2, BBq), blk, GSMEM>>>(
        (bf16*)ch, (bf16*)cl, CTq, sQ, (bf16*)xth, (bf16*)xtl, CCq, sX, CTq,
        (bf16*)woh, (bf16*)wol, 2 * CTq,
        out, NNq, (long long)CCq * NNq, 2 * CTq);
}